// round 4
// baseline (speedup 1.0000x reference)
#include <cuda_runtime.h>
#include <math.h>

#define TPB 256          // threads per block
#define MPT 64           // points per block
#define AS  68           // activation row stride in floats (272B, 16B aligned)
#define KC  16           // k-chunk for weight staging
#define WSS 260          // Ws row stride (floats), 16B aligned

typedef unsigned long long u64;

struct NerfParams {
    const float* pts;
    const float* dirs;
    const float* Wb[8];
    const float* bb[8];
    const float* Wsig; const float* bsig;
    const float* Wrm;  const float* brm;
    const float* Wr0;  const float* br0;
    const float* Wr1;  const float* br1;
    float* out;
    int N;
};

__device__ __forceinline__ void fma2(u64 &acc, u64 a, u64 b){
    asm("fma.rn.f32x2 %0, %1, %2, %0;" : "+l"(acc) : "l"(a), "l"(b));
}
__device__ __forceinline__ u64 pack2(float w){
    u64 r; asm("mov.b64 %0, {%1, %1};" : "=l"(r) : "f"(w)); return r;
}
__device__ __forceinline__ void unpack2(u64 a, float &lo, float &hi){
    asm("mov.b64 {%0, %1}, %2;" : "=f"(lo), "=f"(hi) : "l"(a));
}

// acc layout: acc[jj*8 + i*2 + p] is an f32x2 pair covering points
//   m = i*16 + mq*4 + 2p + {0,1},  for output j = jq*4 + jj.
// buf is k-major SMEM (row stride AS); buf row 0 is k = kbeg.
template<int NOUT>
__device__ __forceinline__ void gemm_pass(u64 acc[32],
        const float* __restrict__ Wg, int wstride,
        int kbeg, int kend, const float* buf, float* Ws,
        int tid, int jq, int mq)
{
    #pragma unroll 1
    for (int k0 = kbeg; k0 < kend; k0 += KC){
        int kc = min(KC, kend - k0);
        __syncthreads();
        // stage weights: Ws[kk][j] = Wg[j][k0+kk]  (global coalesced over kk)
        #pragma unroll 1
        for (int idx = tid; idx < NOUT*KC; idx += TPB){
            int j = idx >> 4, kk = idx & 15;
            if (kk < kc) Ws[kk*WSS + j] = Wg[j*wstride + k0 + kk];
        }
        __syncthreads();
        if (jq*4 < NOUT){
            const float* rowp = buf + (k0 - kbeg)*AS + mq*4;
            const float* wsp  = Ws + jq*4;
            #pragma unroll 1
            for (int kk = 0; kk < kc; kk++){
                float4 wv = *(const float4*)(wsp + kk*WSS);   // 4 weights, 1 LDS.128
                u64 w0 = pack2(wv.x), w1 = pack2(wv.y), w2v = pack2(wv.z), w3 = pack2(wv.w);
                ulonglong2 a0 = *(const ulonglong2*)(rowp);      // m: mq*4 + 0..3
                ulonglong2 a1 = *(const ulonglong2*)(rowp + 16); // m: 16 + mq*4 ..
                ulonglong2 a2 = *(const ulonglong2*)(rowp + 32);
                ulonglong2 a3 = *(const ulonglong2*)(rowp + 48);
                fma2(acc[ 0], a0.x, w0); fma2(acc[ 1], a0.y, w0);
                fma2(acc[ 2], a1.x, w0); fma2(acc[ 3], a1.y, w0);
                fma2(acc[ 4], a2.x, w0); fma2(acc[ 5], a2.y, w0);
                fma2(acc[ 6], a3.x, w0); fma2(acc[ 7], a3.y, w0);
                fma2(acc[ 8], a0.x, w1); fma2(acc[ 9], a0.y, w1);
                fma2(acc[10], a1.x, w1); fma2(acc[11], a1.y, w1);
                fma2(acc[12], a2.x, w1); fma2(acc[13], a2.y, w1);
                fma2(acc[14], a3.x, w1); fma2(acc[15], a3.y, w1);
                fma2(acc[16], a0.x, w2v); fma2(acc[17], a0.y, w2v);
                fma2(acc[18], a1.x, w2v); fma2(acc[19], a1.y, w2v);
                fma2(acc[20], a2.x, w2v); fma2(acc[21], a2.y, w2v);
                fma2(acc[22], a3.x, w2v); fma2(acc[23], a3.y, w2v);
                fma2(acc[24], a0.x, w3); fma2(acc[25], a0.y, w3);
                fma2(acc[26], a1.x, w3); fma2(acc[27], a1.y, w3);
                fma2(acc[28], a2.x, w3); fma2(acc[29], a2.y, w3);
                fma2(acc[30], a3.x, w3); fma2(acc[31], a3.y, w3);
                rowp += AS;
            }
        }
    }
}

template<int NOUT>
__device__ __forceinline__ void writeback_relu(u64 acc[32], const float* __restrict__ bg,
                                               float* dst0, int tid, int jq, int mq)
{
    __syncthreads();   // all reads of the input buffer done before overwrite
    if (jq*4 < NOUT){
        #pragma unroll
        for (int jj = 0; jj < 4; jj++){
            int j = jq*4 + jj;
            float b = bg[j];
            float* dst = dst0 + j*AS + mq*4;
            #pragma unroll
            for (int i = 0; i < 4; i++){
                #pragma unroll
                for (int p = 0; p < 2; p++){
                    float lo, hi; unpack2(acc[jj*8 + i*2 + p], lo, hi);
                    float2 v = make_float2(fmaxf(lo + b, 0.0f), fmaxf(hi + b, 0.0f));
                    *(float2*)(dst + i*16 + 2*p) = v;
                }
            }
        }
    }
}

__device__ __forceinline__ void zero_acc(u64 acc[32]){
    #pragma unroll
    for (int i = 0; i < 32; i++) acc[i] = 0ull;
}

__global__ void __launch_bounds__(TPB, 2) nerf_fused(NerfParams P)
{
    extern __shared__ float sm[];
    float* A  = sm;                 // [256][AS] activations (k-major)
    float* Pe = A  + 256*AS;        // [63][AS]  embedded pts
    float* De = Pe + 63*AS;         // [27][AS]  embedded dirs
    float* Ws = De + 27*AS;         // weight staging: [KC][WSS]
    const int tid = threadIdx.x;
    const int jq  = tid >> 2;       // 0..63  (4 outputs each)
    const int mq  = tid & 3;        // 0..3   (16 points each, interleaved by 4)
    const int g0  = blockIdx.x * MPT;
    const int N   = P.N;

    // ---- embeddings: [x, sin(2^f x)*3, cos(2^f x)*3, ...] f ascending ----
    for (int idx = tid; idx < MPT*3; idx += TPB){
        int m = idx/3, d = idx%3;
        Pe[d*AS+m] = P.pts [(g0+m)*3+d];
        De[d*AS+m] = P.dirs[(g0+m)*3+d];
    }
    for (int idx = tid; idx < MPT*30; idx += TPB){
        int m = idx/30, q = idx%30, f = q/3, d = q%3;
        float x = P.pts[(g0+m)*3+d] * (float)(1<<f);
        float s, c; sincosf(x, &s, &c);
        Pe[(3+f*6+d)*AS+m]   = s;
        Pe[(3+f*6+3+d)*AS+m] = c;
    }
    for (int idx = tid; idx < MPT*12; idx += TPB){
        int m = idx/12, q = idx%12, f = q/3, d = q%3;
        float x = P.dirs[(g0+m)*3+d] * (float)(1<<f);
        float s, c; sincosf(x, &s, &c);
        De[(3+f*6+d)*AS+m]   = s;
        De[(3+f*6+3+d)*AS+m] = c;
    }
    __syncthreads();

    // ---- third output: embedded dirs, out[4N + n*27 + k] ----
    {
        float* outD = P.out + 4ll*N;
        for (int idx = tid; idx < MPT*27; idx += TPB){
            int m = idx/27, k = idx%27;
            outD[(long long)(g0+m)*27 + k] = De[k*AS+m];
        }
    }

    u64 acc[32];

    // ---- layer 0: 63 -> 256 ----
    zero_acc(acc);
    gemm_pass<256>(acc, P.Wb[0], 63, 0, 63, Pe, Ws, tid, jq, mq);
    writeback_relu<256>(acc, P.bb[0], A, tid, jq, mq);

    // ---- layers 1..4: 256 -> 256 ----
    #pragma unroll 1
    for (int L = 1; L <= 4; L++){
        zero_acc(acc);
        gemm_pass<256>(acc, P.Wb[L], 256, 0, 256, A, Ws, tid, jq, mq);
        writeback_relu<256>(acc, P.bb[L], A, tid, jq, mq);
    }

    // ---- layer 5 with skip: [p(63), base(256)] -> 256 ----
    zero_acc(acc);
    gemm_pass<256>(acc, P.Wb[5], 319, 0, 63, Pe, Ws, tid, jq, mq);
    gemm_pass<256>(acc, P.Wb[5], 319, 63, 319, A, Ws, tid, jq, mq);
    writeback_relu<256>(acc, P.bb[5], A, tid, jq, mq);

    // ---- layers 6, 7: 256 -> 256 ----
    #pragma unroll 1
    for (int L = 6; L <= 7; L++){
        zero_acc(acc);
        gemm_pass<256>(acc, P.Wb[L], 256, 0, 256, A, Ws, tid, jq, mq);
        writeback_relu<256>(acc, P.bb[L], A, tid, jq, mq);
    }

    // ---- sigma = base @ Wsig.T + bsig (SIGMA_MUL=0) ----
    __syncthreads();
    Ws[tid] = P.Wsig[tid];          // stage the 256-vector
    __syncthreads();
    if (tid < MPT){
        float s = P.bsig[0];
        #pragma unroll 8
        for (int k = 0; k < 256; k++) s += A[k*AS+tid] * Ws[k];
        P.out[3ll*N + g0 + tid] = s;
    }
    // (next gemm_pass's first __syncthreads orders Ws reuse after these reads)

    // ---- base_remap = relu(base @ Wrm.T + brm) ----
    zero_acc(acc);
    gemm_pass<256>(acc, P.Wrm, 256, 0, 256, A, Ws, tid, jq, mq);
    writeback_relu<256>(acc, P.brm, A, tid, jq, mq);

    // ---- rgb_fea = relu([remap(256), d(27)] @ Wr0.T + br0), 128 outputs ----
    zero_acc(acc);
    gemm_pass<128>(acc, P.Wr0, 283, 0, 256, A, Ws, tid, jq, mq);
    gemm_pass<128>(acc, P.Wr0, 283, 256, 283, De, Ws, tid, jq, mq);
    writeback_relu<128>(acc, P.br0, A, tid, jq, mq);   // overwrites A rows 0..127
    __syncthreads();

    // ---- rgb = sigmoid(fea @ Wr1.T + br1) ----
    for (int idx = tid; idx < 384; idx += TPB) Ws[idx] = P.Wr1[idx];
    __syncthreads();
    if (tid < MPT){
        #pragma unroll
        for (int c = 0; c < 3; c++){
            float a = P.br1[c];
            #pragma unroll 8
            for (int k = 0; k < 128; k++) a += A[k*AS+tid] * Ws[c*128+k];
            P.out[(long long)(g0+tid)*3 + c] = 1.0f/(1.0f + expf(-a));
        }
    }
}

extern "C" void kernel_launch(void* const* d_in, const int* in_sizes, int n_in,
                              void* d_out, int out_size)
{
    NerfParams p;
    p.pts  = (const float*)d_in[0];
    p.dirs = (const float*)d_in[1];
    for (int i = 0; i < 8; i++){
        p.Wb[i] = (const float*)d_in[2 + 2*i];
        p.bb[i] = (const float*)d_in[3 + 2*i];
    }
    p.Wsig = (const float*)d_in[18]; p.bsig = (const float*)d_in[19];
    p.Wrm  = (const float*)d_in[20]; p.brm  = (const float*)d_in[21];
    p.Wr0  = (const float*)d_in[22]; p.br0  = (const float*)d_in[23];
    p.Wr1  = (const float*)d_in[24]; p.br1  = (const float*)d_in[25];
    p.out  = (float*)d_out;
    p.N    = in_sizes[0] / 3;

    size_t smem = (size_t)(256*AS + 63*AS + 27*AS + KC*WSS + 192) * sizeof(float);
    cudaFuncSetAttribute(nerf_fused, cudaFuncAttributeMaxDynamicSharedMemorySize, (int)smem);

    int blocks = p.N / MPT;   // 262144/64 = 4096
    nerf_fused<<<blocks, TPB, smem>>>(p);
}

// round 5
// speedup vs baseline: 1.5724x; 1.5724x over previous
#include <cuda_runtime.h>
#include <math.h>

#define TPB 256          // threads per block
#define MPT 64           // points per block
#define AS  68           // activation row stride in floats (272B, 16B aligned)
#define KC  16           // k-chunk for weight staging
#define WSS 260          // Ws row stride (floats), 16B aligned

typedef unsigned long long u64;

struct NerfParams {
    const float* pts;
    const float* dirs;
    const float* Wb[8];
    const float* bb[8];
    const float* Wsig; const float* bsig;
    const float* Wrm;  const float* brm;
    const float* Wr0;  const float* br0;
    const float* Wr1;  const float* br1;
    float* out;
    int N;
};

__device__ __forceinline__ void fma2(u64 &acc, u64 a, u64 b){
    asm("fma.rn.f32x2 %0, %1, %2, %0;" : "+l"(acc) : "l"(a), "l"(b));
}
__device__ __forceinline__ u64 pack2(float w){
    u64 r; asm("mov.b64 %0, {%1, %1};" : "=l"(r) : "f"(w)); return r;
}
__device__ __forceinline__ void unpack2(u64 a, float &lo, float &hi){
    asm("mov.b64 {%0, %1}, %2;" : "=f"(lo), "=f"(hi) : "l"(a));
}

// acc layout: acc[jj*8 + i*2 + p] is an f32x2 pair covering points
//   m = i*16 + mq*4 + 2p + {0,1},  for output j = jq*4 + jj.
// buf is k-major SMEM (row stride AS); buf row 0 is k = kbeg.
template<int NOUT>
__device__ __forceinline__ void gemm_pass(u64 acc[32],
        const float* __restrict__ Wg, int wstride,
        int kbeg, int kend, const float* buf, float* Ws,
        int tid, int jq, int mq)
{
    #pragma unroll 1
    for (int k0 = kbeg; k0 < kend; k0 += KC){
        int kc = min(KC, kend - k0);
        __syncthreads();
        // stage weights: Ws[kk][j] = Wg[j][k0+kk]  (global coalesced over kk)
        #pragma unroll 1
        for (int idx = tid; idx < NOUT*KC; idx += TPB){
            int j = idx >> 4, kk = idx & 15;
            if (kk < kc) Ws[kk*WSS + j] = Wg[j*wstride + k0 + kk];
        }
        __syncthreads();
        if (jq*4 < NOUT){
            const float* rowp = buf + (k0 - kbeg)*AS + mq*4;
            const float* wsp  = Ws + jq*4;
            #pragma unroll 1
            for (int kk = 0; kk < kc; kk++){
                float4 wv = *(const float4*)(wsp + kk*WSS);   // 4 weights, 1 LDS.128
                u64 w0 = pack2(wv.x), w1 = pack2(wv.y), w2v = pack2(wv.z), w3 = pack2(wv.w);
                ulonglong2 a0 = *(const ulonglong2*)(rowp);      // m: mq*4 + 0..3
                ulonglong2 a1 = *(const ulonglong2*)(rowp + 16); // m: 16 + mq*4 ..
                ulonglong2 a2 = *(const ulonglong2*)(rowp + 32);
                ulonglong2 a3 = *(const ulonglong2*)(rowp + 48);
                fma2(acc[ 0], a0.x, w0); fma2(acc[ 1], a0.y, w0);
                fma2(acc[ 2], a1.x, w0); fma2(acc[ 3], a1.y, w0);
                fma2(acc[ 4], a2.x, w0); fma2(acc[ 5], a2.y, w0);
                fma2(acc[ 6], a3.x, w0); fma2(acc[ 7], a3.y, w0);
                fma2(acc[ 8], a0.x, w1); fma2(acc[ 9], a0.y, w1);
                fma2(acc[10], a1.x, w1); fma2(acc[11], a1.y, w1);
                fma2(acc[12], a2.x, w1); fma2(acc[13], a2.y, w1);
                fma2(acc[14], a3.x, w1); fma2(acc[15], a3.y, w1);
                fma2(acc[16], a0.x, w2v); fma2(acc[17], a0.y, w2v);
                fma2(acc[18], a1.x, w2v); fma2(acc[19], a1.y, w2v);
                fma2(acc[20], a2.x, w2v); fma2(acc[21], a2.y, w2v);
                fma2(acc[22], a3.x, w2v); fma2(acc[23], a3.y, w2v);
                fma2(acc[24], a0.x, w3); fma2(acc[25], a0.y, w3);
                fma2(acc[26], a1.x, w3); fma2(acc[27], a1.y, w3);
                fma2(acc[28], a2.x, w3); fma2(acc[29], a2.y, w3);
                fma2(acc[30], a3.x, w3); fma2(acc[31], a3.y, w3);
                rowp += AS;
            }
        }
    }
}

template<int NOUT>
__device__ __forceinline__ void writeback_relu(u64 acc[32], const float* __restrict__ bg,
                                               float* dst0, int tid, int jq, int mq)
{
    __syncthreads();   // all reads of the input buffer done before overwrite
    if (jq*4 < NOUT){
        #pragma unroll
        for (int jj = 0; jj < 4; jj++){
            int j = jq*4 + jj;
            float b = bg[j];
            float* dst = dst0 + j*AS + mq*4;
            #pragma unroll
            for (int i = 0; i < 4; i++){
                #pragma unroll
                for (int p = 0; p < 2; p++){
                    float lo, hi; unpack2(acc[jj*8 + i*2 + p], lo, hi);
                    float2 v = make_float2(fmaxf(lo + b, 0.0f), fmaxf(hi + b, 0.0f));
                    *(float2*)(dst + i*16 + 2*p) = v;
                }
            }
        }
    }
}

__device__ __forceinline__ void zero_acc(u64 acc[32]){
    #pragma unroll
    for (int i = 0; i < 32; i++) acc[i] = 0ull;
}

__global__ void __launch_bounds__(TPB, 2) nerf_fused(NerfParams P)
{
    extern __shared__ float sm[];
    float* A  = sm;                 // [256][AS] activations (k-major)
    float* Pe = A  + 256*AS;        // [63][AS]  embedded pts
    float* De = Pe + 63*AS;         // [27][AS]  embedded dirs
    float* Ws = De + 27*AS;         // weight staging: [KC][WSS]
    const int tid = threadIdx.x;
    const int jq  = tid >> 2;       // 0..63  (4 outputs each)
    const int mq  = tid & 3;        // 0..3   (16 points each, interleaved by 4)
    const int g0  = blockIdx.x * MPT;
    const int N   = P.N;

    // ---- embeddings: [x, sin(2^f x)*3, cos(2^f x)*3, ...] f ascending ----
    for (int idx = tid; idx < MPT*3; idx += TPB){
        int m = idx/3, d = idx%3;
        Pe[d*AS+m] = P.pts [(g0+m)*3+d];
        De[d*AS+m] = P.dirs[(g0+m)*3+d];
    }
    for (int idx = tid; idx < MPT*30; idx += TPB){
        int m = idx/30, q = idx%30, f = q/3, d = q%3;
        float x = P.pts[(g0+m)*3+d] * (float)(1<<f);
        float s, c; sincosf(x, &s, &c);
        Pe[(3+f*6+d)*AS+m]   = s;
        Pe[(3+f*6+3+d)*AS+m] = c;
    }
    for (int idx = tid; idx < MPT*12; idx += TPB){
        int m = idx/12, q = idx%12, f = q/3, d = q%3;
        float x = P.dirs[(g0+m)*3+d] * (float)(1<<f);
        float s, c; sincosf(x, &s, &c);
        De[(3+f*6+d)*AS+m]   = s;
        De[(3+f*6+3+d)*AS+m] = c;
    }
    __syncthreads();

    // ---- third output: embedded dirs, out[4N + n*27 + k] ----
    {
        float* outD = P.out + 4ll*N;
        for (int idx = tid; idx < MPT*27; idx += TPB){
            int m = idx/27, k = idx%27;
            outD[(long long)(g0+m)*27 + k] = De[k*AS+m];
        }
    }

    u64 acc[32];

    // ---- layer 0: 63 -> 256 ----
    zero_acc(acc);
    gemm_pass<256>(acc, P.Wb[0], 63, 0, 63, Pe, Ws, tid, jq, mq);
    writeback_relu<256>(acc, P.bb[0], A, tid, jq, mq);

    // ---- layers 1..4: 256 -> 256 ----
    #pragma unroll 1
    for (int L = 1; L <= 4; L++){
        zero_acc(acc);
        gemm_pass<256>(acc, P.Wb[L], 256, 0, 256, A, Ws, tid, jq, mq);
        writeback_relu<256>(acc, P.bb[L], A, tid, jq, mq);
    }

    // ---- layer 5 with skip: [p(63), base(256)] -> 256 ----
    zero_acc(acc);
    gemm_pass<256>(acc, P.Wb[5], 319, 0, 63, Pe, Ws, tid, jq, mq);
    gemm_pass<256>(acc, P.Wb[5], 319, 63, 319, A, Ws, tid, jq, mq);
    writeback_relu<256>(acc, P.bb[5], A, tid, jq, mq);

    // ---- layers 6, 7: 256 -> 256 ----
    #pragma unroll 1
    for (int L = 6; L <= 7; L++){
        zero_acc(acc);
        gemm_pass<256>(acc, P.Wb[L], 256, 0, 256, A, Ws, tid, jq, mq);
        writeback_relu<256>(acc, P.bb[L], A, tid, jq, mq);
    }

    // ---- sigma = base @ Wsig.T + bsig (SIGMA_MUL=0) ----
    __syncthreads();
    Ws[tid] = P.Wsig[tid];          // stage the 256-vector
    __syncthreads();
    if (tid < MPT){
        float s = P.bsig[0];
        #pragma unroll 8
        for (int k = 0; k < 256; k++) s += A[k*AS+tid] * Ws[k];
        P.out[3ll*N + g0 + tid] = s;
    }
    // (next gemm_pass's first __syncthreads orders Ws reuse after these reads)

    // ---- base_remap = relu(base @ Wrm.T + brm) ----
    zero_acc(acc);
    gemm_pass<256>(acc, P.Wrm, 256, 0, 256, A, Ws, tid, jq, mq);
    writeback_relu<256>(acc, P.brm, A, tid, jq, mq);

    // ---- rgb_fea = relu([remap(256), d(27)] @ Wr0.T + br0), 128 outputs ----
    zero_acc(acc);
    gemm_pass<128>(acc, P.Wr0, 283, 0, 256, A, Ws, tid, jq, mq);
    gemm_pass<128>(acc, P.Wr0, 283, 256, 283, De, Ws, tid, jq, mq);
    writeback_relu<128>(acc, P.br0, A, tid, jq, mq);   // overwrites A rows 0..127
    __syncthreads();

    // ---- rgb = sigmoid(fea @ Wr1.T + br1) ----
    for (int idx = tid; idx < 384; idx += TPB) Ws[idx] = P.Wr1[idx];
    __syncthreads();
    if (tid < MPT){
        #pragma unroll
        for (int c = 0; c < 3; c++){
            float a = P.br1[c];
            #pragma unroll 8
            for (int k = 0; k < 128; k++) a += A[k*AS+tid] * Ws[c*128+k];
            P.out[(long long)(g0+tid)*3 + c] = 1.0f/(1.0f + expf(-a));
        }
    }
}

extern "C" void kernel_launch(void* const* d_in, const int* in_sizes, int n_in,
                              void* d_out, int out_size)
{
    NerfParams p;
    p.pts  = (const float*)d_in[0];
    p.dirs = (const float*)d_in[1];
    for (int i = 0; i < 8; i++){
        p.Wb[i] = (const float*)d_in[2 + 2*i];
        p.bb[i] = (const float*)d_in[3 + 2*i];
    }
    p.Wsig = (const float*)d_in[18]; p.bsig = (const float*)d_in[19];
    p.Wrm  = (const float*)d_in[20]; p.brm  = (const float*)d_in[21];
    p.Wr0  = (const float*)d_in[22]; p.br0  = (const float*)d_in[23];
    p.Wr1  = (const float*)d_in[24]; p.br1  = (const float*)d_in[25];
    p.out  = (float*)d_out;
    p.N    = in_sizes[0] / 3;

    size_t smem = (size_t)(256*AS + 63*AS + 27*AS + KC*WSS + 192) * sizeof(float);
    cudaFuncSetAttribute(nerf_fused, cudaFuncAttributeMaxDynamicSharedMemorySize, (int)smem);

    int blocks = p.N / MPT;   // 262144/64 = 4096
    nerf_fused<<<blocks, TPB, smem>>>(p);
}

// round 9
// speedup vs baseline: 3.7637x; 2.3935x over previous
#include <cuda_runtime.h>
#include <cuda_bf16.h>
#include <cstdint>
#include <math.h>

#define NCHUNK 308
#define SM_AHI 0
#define SM_ALO 81920
#define SM_W   163840
#define SM_BIAS 196608
#define SM_WSIG 206848
#define SM_WR1  207872
#define SM_SCAL 209408
#define SM_MBAR 209424
#define SM_TOTAL 209456

__device__ __forceinline__ uint32_t smem_u32(const void* p){
    uint32_t a; asm("{ .reg .u64 t; cvta.to.shared.u64 t, %1; cvt.u32.u64 %0, t; }" : "=r"(a) : "l"(p)); return a;
}
#define MB_INIT(m,c) asm volatile("mbarrier.init.shared.b64 [%0], %1;" :: "r"(m), "r"((uint32_t)(c)) : "memory")
#define MB_EXTX(m,b) asm volatile("mbarrier.arrive.expect_tx.shared.b64 _, [%0], %1;" :: "r"(m), "r"((uint32_t)(b)) : "memory")
#define MB_WAIT(m,ph) do{ uint32_t _m=(m),_p=(ph),_d; \
    asm volatile("{\n\t.reg .pred p;\n\tmbarrier.try_wait.parity.acquire.cta.shared::cta.b64 p, [%1], %2;\n\tselp.b32 %0,1,0,p;\n\t}" : "=r"(_d) : "r"(_m), "r"(_p) : "memory"); \
    if(!_d){ asm volatile("{\n\t.reg .pred P1;\n\tWL_%=:\n\tmbarrier.try_wait.parity.acquire.cta.shared::cta.b64 P1, [%0], %1, 0x989680;\n\t@P1 bra.uni WD_%=;\n\tbra.uni WL_%=;\n\tWD_%=:\n\t}" :: "r"(_m), "r"(_p) : "memory"); } }while(0)
__device__ __forceinline__ void bulk_g2s(uint32_t dst, const void* src, uint32_t bytes, uint32_t mbar){
    asm volatile("cp.async.bulk.shared::cluster.global.mbarrier::complete_tx::bytes [%0], [%1], %2, [%3];"
        :: "r"(dst), "l"(src), "r"(bytes), "r"(mbar) : "memory");
}
#define LDMX2(r,a) asm volatile("ldmatrix.sync.aligned.m8n8.x2.shared.b16 {%0,%1}, [%2];" : "=r"((r)[0]),"=r"((r)[1]) : "r"(a))
#define LDMX4(r,a) asm volatile("ldmatrix.sync.aligned.m8n8.x4.shared.b16 {%0,%1,%2,%3}, [%4];" \
    : "=r"((r)[0]),"=r"((r)[1]),"=r"((r)[2]),"=r"((r)[3]) : "r"(a))
#define MMA888(c,a,b) asm volatile("mma.sync.aligned.m16n8k8.row.col.f32.bf16.bf16.f32 {%0,%1,%2,%3},{%4,%5},{%6},{%0,%1,%2,%3};" \
    : "+f"((c)[0]),"+f"((c)[1]),"+f"((c)[2]),"+f"((c)[3]) : "r"((a)[0]),"r"((a)[1]), "r"(b))

__device__ __forceinline__ void packhl(float v0, float v1, uint32_t &hi, uint32_t &lo){
    __nv_bfloat16 h0=__float2bfloat16(v0), h1=__float2bfloat16(v1);
    __nv_bfloat16 e0=__float2bfloat16(v0-__bfloat162float(h0)), e1=__float2bfloat16(v1-__bfloat162float(h1));
    hi=(uint32_t)__bfloat16_as_ushort(h0)|((uint32_t)__bfloat16_as_ushort(h1)<<16);
    lo=(uint32_t)__bfloat16_as_ushort(e0)|((uint32_t)__bfloat16_as_ushort(e1)<<16);
}
// segment tables: 12 segments over 10 GEMM layers, k8 chunks
__constant__ unsigned char sg_layer[12]={0,1,2,3,4,5,5,6,7,8,9,9};
__constant__ short sg_cnt[12]={8,32,32,32,32,8,32,32,32,32,32,4};
__constant__ short sg_cum[12]={0,8,40,72,104,136,144,176,208,240,272,304};
__constant__ unsigned char sg_akt[12]={32,0,0,0,0,32,0,0,0,0,0,32};
__constant__ unsigned char sg_first[12]={1,1,1,1,1,1,0,1,1,1,1,0};
__constant__ unsigned char sg_end[12]={1,1,1,1,1,0,1,1,1,1,0,1};
__constant__ unsigned char sg_w[12]={0,1,2,3,4,5,5,6,7,8,9,9};
__constant__ short sg_wcol[12]={0,0,0,0,0,0,63,0,0,0,0,256};
__constant__ short sg_kmax[12]={63,256,256,256,256,63,256,256,256,256,256,27};
__constant__ short sg_wstr[12]={63,256,256,256,256,319,319,256,256,256,283,283};
__constant__ short sg_nval[12]={256,256,256,256,256,256,256,256,256,256,128,128};

__device__ __align__(1024) unsigned char g_ws[NCHUNK*8192];

struct PrepParams { const float* w[10]; };
__global__ void prep(PrepParams pp){
    int c = blockIdx.x, s = 11;
    for (int i = 1; i < 12; i++) if (c < sg_cum[i]){ s = i-1; break; }
    int ci = c - sg_cum[s];
    const float* W = pp.w[sg_w[s]];
    int kval = sg_kmax[s] - 8*ci; if (kval > 8) kval = 8;
    int nval = sg_nval[s], ws = sg_wstr[s], col0 = sg_wcol[s] + ci*8;
    unsigned char* dhi = g_ws + (long long)c*8192;
    unsigned char* dlo = dhi + 4096;
    for (int idx = threadIdx.x; idx < 2048; idx += blockDim.x){
        int n = idx>>3, kk = idx&7;
        float w = (kk < kval && n < nval) ? W[n*ws + col0 + kk] : 0.f;
        __nv_bfloat16 h = __float2bfloat16(w);
        __nv_bfloat16 l = __float2bfloat16(w - __bfloat162float(h));
        uint32_t off = (uint32_t)((n>>3)*128 + (n&7)*16 + kk*2);
        *(__nv_bfloat16*)(dhi+off) = h; *(__nv_bfloat16*)(dlo+off) = l;
    }
}

struct MainParams {
    const float* pts; const float* dirs;
    const float* bias[10];           // bb0..7, brm, br0
    const float* Wsig; const float* bsig;
    const float* Wr1;  const float* br1;
    float* out; int N;
};

__device__ __forceinline__ float embed_val(const float* base, int g0, int m, int k){
    if (k < 3) return base[(g0+m)*3+k];
    int q = k-3, f = q/6, rr = q - f*6, d = rr%3;
    float x = base[(g0+m)*3+d] * (float)(1<<f);
    return (rr < 3) ? sinf(x) : cosf(x);
}
__device__ __forceinline__ void store_a(unsigned char* smem, int m, int col, float v){
    uint32_t off = (uint32_t)((((m>>3)*40 + (col>>3))<<7) + (m&7)*16 + (col&7)*2);
    __nv_bfloat16 h = __float2bfloat16(v), l = __float2bfloat16(v - __bfloat162float(h));
    *(__nv_bfloat16*)(smem+SM_AHI+off) = h;
    *(__nv_bfloat16*)(smem+SM_ALO+off) = l;
}
__device__ __forceinline__ float read_a(const unsigned char* smem, int m, int k){
    uint32_t off = (uint32_t)((((m>>3)*40 + (k>>3))<<7) + (m&7)*16 + (k&7)*2);
    return __bfloat162float(*(const __nv_bfloat16*)(smem+SM_AHI+off))
         + __bfloat162float(*(const __nv_bfloat16*)(smem+SM_ALO+off));
}

__global__ void __launch_bounds__(512,1) nerf_mma(MainParams P)
{
    extern __shared__ __align__(1024) unsigned char smem[];
    const uint32_t sb = smem_u32(smem), mb = sb + SM_MBAR;
    float* biasS = (float*)(smem+SM_BIAS);
    float* WsigS = (float*)(smem+SM_WSIG);
    float* Wr1S  = (float*)(smem+SM_WR1);
    float* scalS = (float*)(smem+SM_SCAL);
    const int tid = threadIdx.x, lane = tid&31, wid = tid>>5;
    const int ms = wid&3, ns = wid>>2;
    const int gp0 = blockIdx.x*128;
    const long long N = P.N;

    if (tid == 0){ MB_INIT(mb,1); MB_INIT(mb+8,1); }
    __syncthreads();
    if (tid == 0){
        MB_EXTX(mb,8192);   bulk_g2s(sb+SM_W,       g_ws,      8192, mb);
        MB_EXTX(mb+8,8192); bulk_g2s(sb+SM_W+16384, g_ws+8192, 8192, mb+8);
    }
    for (int i = tid*16; i < 163840; i += 512*16) *(uint4*)(smem+i) = make_uint4(0,0,0,0);
    for (int i = tid; i < 2048; i += 512){ int l = i>>8; biasS[i] = P.bias[l][i&255]; }
    for (int i = tid; i < 256; i += 512) biasS[2048+i] = P.bias[8][i];
    for (int i = tid; i < 256; i += 512) biasS[2304+i] = (i < 128) ? P.bias[9][i] : 0.f;
    for (int i = tid; i < 256; i += 512) WsigS[i] = P.Wsig[i];
    for (int i = tid; i < 384; i += 512) Wr1S[i] = P.Wr1[i];
    if (tid == 0){ scalS[0]=P.bsig[0]; scalS[1]=P.br1[0]; scalS[2]=P.br1[1]; scalS[3]=P.br1[2]; }
    __syncthreads();
    for (int idx = tid; idx < 128*63; idx += 512){
        int m = idx/63, k = idx - m*63;
        store_a(smem, m, 256+k, embed_val(P.pts, gp0, m, k));
    }
    {
        float* outD = P.out + 4*N;
        for (int idx = tid; idx < 128*27; idx += 512){
            int m = idx/27, k = idx - m*27;
            outD[(long long)(gp0+m)*27 + k] = embed_val(P.dirs, gp0, m, k);
        }
    }
    __syncthreads();

    float acc[64];
    int c = 0; uint32_t ph0 = 0, ph1 = 0;
    #pragma unroll 1
    for (int s = 0; s < 12; s++){
        const int cnt = sg_cnt[s], akt0 = sg_akt[s], layer = sg_layer[s];
        if (sg_first[s]){
            #pragma unroll
            for (int i = 0; i < 64; i++) acc[i] = 0.f;
        }
        #pragma unroll 1
        for (int ci = 0; ci < cnt; ci++, c++){
            int buf = c&1;
            if (buf){ MB_WAIT(mb+8, ph1); ph1 ^= 1; } else { MB_WAIT(mb, ph0); ph0 ^= 1; }
            uint32_t wb = sb + SM_W + buf*16384;
            int kt = akt0 + ci;
            uint32_t ah[2][2], al[2][2];
            #pragma unroll
            for (int mh = 0; mh < 2; mh++){
                uint32_t ao = (uint32_t)((((ms*4 + mh*2 + ((lane>>3)&1))*40 + kt)<<7) + (lane&7)*16);
                LDMX2(ah[mh], sb + SM_AHI + ao);
                LDMX2(al[mh], sb + SM_ALO + ao);
            }
            #pragma unroll
            for (int g = 0; g < 2; g++){
                uint32_t bo = (uint32_t)((ns*8 + g*4 + (lane>>3))*128 + (lane&7)*16);
                uint32_t bh[4], bl[4];
                LDMX4(bh, wb + bo);
                LDMX4(bl, wb + 4096 + bo);
                #pragma unroll
                for (int q = 0; q < 4; q++)
                    #pragma unroll
                    for (int mh = 0; mh < 2; mh++){
                        float* a4 = acc + ((g*4+q)*2 + mh)*4;
                        MMA888(a4, ah[mh], bh[q]);
                        MMA888(a4, al[mh], bh[q]);
                        MMA888(a4, ah[mh], bl[q]);
                    }
            }
            __syncthreads();
            if (tid == 0 && c+2 < NCHUNK){
                MB_EXTX(mb + buf*8, 8192);
                bulk_g2s(wb, g_ws + (long long)(c+2)*8192, 8192, mb + buf*8);
            }
        }
        if (sg_end[s]){
            const float* bp = biasS + ((layer <= 7) ? layer*256 : (layer == 8 ? 2048 : 2304));
            #pragma unroll
            for (int nti = 0; nti < 8; nti++)
                #pragma unroll
                for (int mh = 0; mh < 2; mh++){
                    float* a4 = acc + (nti*2 + mh)*4;
                    int n0 = ns*64 + nti*8 + (lane&3)*2;
                    int mr = ms*32 + mh*16 + (lane>>2);
                    float b0 = bp[n0], b1 = bp[n0+1];
                    int ktw = ns*8 + nti;
                    float v0 = fmaxf(a4[0]+b0,0.f), v1 = fmaxf(a4[1]+b1,0.f);
                    float v2 = fmaxf(a4[2]+b0,0.f), v3 = fmaxf(a4[3]+b1,0.f);
                    uint32_t h, lo2;
                    uint32_t o0 = (uint32_t)((((mr>>3)*40 + ktw)<<7) + (mr&7)*16 + (lane&3)*4);
                    int m2 = mr + 8;
                    uint32_t o1 = (uint32_t)((((m2>>3)*40 + ktw)<<7) + (m2&7)*16 + (lane&3)*4);
                    packhl(v0, v1, h, lo2);
                    *(uint32_t*)(smem+SM_AHI+o0) = h; *(uint32_t*)(smem+SM_ALO+o0) = lo2;
                    packhl(v2, v3, h, lo2);
                    *(uint32_t*)(smem+SM_AHI+o1) = h; *(uint32_t*)(smem+SM_ALO+o1) = lo2;
                }
            if (layer == 5){
                for (int idx = tid; idx < 128*27; idx += 512){
                    int m = idx/27, k = idx - m*27;
                    store_a(smem, m, 256+k, embed_val(P.dirs, gp0, m, k));
                }
            }
            __syncthreads();
            if (layer == 7 && tid < 128){
                int m = tid; float ssum = scalS[0];
                #pragma unroll 8
                for (int k = 0; k < 256; k++) ssum = fmaf(read_a(smem, m, k), WsigS[k], ssum);
                P.out[3*N + gp0 + m] = ssum;
            }
            if (layer == 9 && tid < 128){
                int m = tid; float r0 = scalS[1], r1 = scalS[2], r2 = scalS[3];
                #pragma unroll 8
                for (int k = 0; k < 128; k++){
                    float av = read_a(smem, m, k);
                    r0 = fmaf(av, Wr1S[k], r0);
                    r1 = fmaf(av, Wr1S[128+k], r1);
                    r2 = fmaf(av, Wr1S[256+k], r2);
                }
                long long gm = gp0 + m;
                P.out[gm*3+0] = 1.f/(1.f + expf(-r0));
                P.out[gm*3+1] = 1.f/(1.f + expf(-r1));
                P.out[gm*3+2] = 1.f/(1.f + expf(-r2));
            }
        }
    }
}

extern "C" void kernel_launch(void* const* d_in, const int* in_sizes, int n_in,
                              void* d_out, int out_size)
{
    PrepParams pp;
    for (int i = 0; i < 8; i++) pp.w[i] = (const float*)d_in[2 + 2*i];
    pp.w[8] = (const float*)d_in[20];
    pp.w[9] = (const float*)d_in[22];

    MainParams mp;
    mp.pts  = (const float*)d_in[0];
    mp.dirs = (const float*)d_in[1];
    for (int i = 0; i < 8; i++) mp.bias[i] = (const float*)d_in[3 + 2*i];
    mp.bias[8] = (const float*)d_in[21];     // brm
    mp.bias[9] = (const float*)d_in[23];     // br0
    mp.Wsig = (const float*)d_in[18]; mp.bsig = (const float*)d_in[19];
    mp.Wr1  = (const float*)d_in[24]; mp.br1  = (const float*)d_in[25];
    mp.out  = (float*)d_out;
    mp.N    = in_sizes[0] / 3;

    prep<<<NCHUNK, 256>>>(pp);
    cudaFuncSetAttribute(nerf_mma, cudaFuncAttributeMaxDynamicSharedMemorySize, SM_TOTAL);
    nerf_mma<<<mp.N/128, 512, SM_TOTAL>>>(mp);
}

// round 10
// speedup vs baseline: 9.6456x; 2.5628x over previous
#include <cuda_runtime.h>
#include <cuda_fp16.h>
#include <cstdint>
#include <math.h>

#define NCHUNK 154
#define SM_A    0
#define SM_W    81920
#define SM_BIAS 147456
#define SM_WSIG 157696
#define SM_WR1  158720
#define SM_SCAL 160256
#define SM_MBAR 160272
#define SM_TOTAL 160320

__device__ __forceinline__ uint32_t smem_u32(const void* p){
    uint32_t a; asm("{ .reg .u64 t; cvta.to.shared.u64 t, %1; cvt.u32.u64 %0, t; }" : "=r"(a) : "l"(p)); return a;
}
#define MB_INIT(m,c) asm volatile("mbarrier.init.shared.b64 [%0], %1;" :: "r"(m), "r"((uint32_t)(c)) : "memory")
#define MB_EXTX(m,b) asm volatile("mbarrier.arrive.expect_tx.shared.b64 _, [%0], %1;" :: "r"(m), "r"((uint32_t)(b)) : "memory")
#define MB_WAIT(m,ph) do{ uint32_t _m=(m),_p=(ph),_d; \
    asm volatile("{\n\t.reg .pred p;\n\tmbarrier.try_wait.parity.acquire.cta.shared::cta.b64 p, [%1], %2;\n\tselp.b32 %0,1,0,p;\n\t}" : "=r"(_d) : "r"(_m), "r"(_p) : "memory"); \
    if(!_d){ asm volatile("{\n\t.reg .pred P1;\n\tWL_%=:\n\tmbarrier.try_wait.parity.acquire.cta.shared::cta.b64 P1, [%0], %1, 0x989680;\n\t@P1 bra.uni WD_%=;\n\tbra.uni WL_%=;\n\tWD_%=:\n\t}" :: "r"(_m), "r"(_p) : "memory"); } }while(0)
__device__ __forceinline__ void bulk_g2s(uint32_t dst, const void* src, uint32_t bytes, uint32_t mbar){
    asm volatile("cp.async.bulk.shared::cluster.global.mbarrier::complete_tx::bytes [%0], [%1], %2, [%3];"
        :: "r"(dst), "l"(src), "r"(bytes), "r"(mbar) : "memory");
}
#define LDMX4(r,a) asm volatile("ldmatrix.sync.aligned.m8n8.x4.shared.b16 {%0,%1,%2,%3}, [%4];" \
    : "=r"((r)[0]),"=r"((r)[1]),"=r"((r)[2]),"=r"((r)[3]) : "r"(a))
#define MMA16816(c,a,b0,b1) asm volatile( \
    "mma.sync.aligned.m16n8k16.row.col.f32.f16.f16.f32 {%0,%1,%2,%3},{%4,%5,%6,%7},{%8,%9},{%0,%1,%2,%3};" \
    : "+f"((c)[0]),"+f"((c)[1]),"+f"((c)[2]),"+f"((c)[3]) \
    : "r"((a)[0]),"r"((a)[1]),"r"((a)[2]),"r"((a)[3]), "r"(b0),"r"(b1))

__device__ __forceinline__ uint32_t packh2(float v0, float v1){
    __half2 h = __floats2half2_rn(v0, v1);
    return *reinterpret_cast<uint32_t*>(&h);
}

// segment tables: 12 segments over 10 GEMM layers, k16 chunks
__constant__ unsigned char sg_layer[12]={0,1,2,3,4,5,5,6,7,8,9,9};
__constant__ short sg_cnt[12]={4,16,16,16,16,4,16,16,16,16,16,2};
__constant__ short sg_cum[12]={0,4,20,36,52,68,72,88,104,120,136,152};
__constant__ unsigned char sg_akt[12]={32,0,0,0,0,32,0,0,0,0,0,32};
__constant__ unsigned char sg_first[12]={1,1,1,1,1,1,0,1,1,1,1,0};
__constant__ unsigned char sg_end[12]={1,1,1,1,1,0,1,1,1,1,0,1};
__constant__ unsigned char sg_w[12]={0,1,2,3,4,5,5,6,7,8,9,9};
__constant__ short sg_wcol[12]={0,0,0,0,0,0,63,0,0,0,0,256};
__constant__ short sg_kmax[12]={63,256,256,256,256,63,256,256,256,256,256,27};
__constant__ short sg_wstr[12]={63,256,256,256,256,319,319,256,256,256,283,283};
__constant__ short sg_nval[12]={256,256,256,256,256,256,256,256,256,256,128,128};

__device__ __align__(1024) unsigned char g_ws[NCHUNK*16384];

struct PrepParams { const float* w[10]; };
__global__ void prep(PrepParams pp){
    int c = blockIdx.x, s = 11;
    for (int i = 1; i < 12; i++) if (c < sg_cum[i]){ s = i-1; break; }
    int ci = c - sg_cum[s];
    const float* W = pp.w[sg_w[s]];
    int kval = sg_kmax[s] - 16*ci; if (kval > 16) kval = 16;
    int nval = sg_nval[s], ws = sg_wstr[s], col0 = sg_wcol[s] + ci*16;
    unsigned char* dhi = g_ws + (long long)c*16384;
    unsigned char* dlo = dhi + 8192;
    for (int idx = threadIdx.x; idx < 4096; idx += blockDim.x){
        int n = idx>>4, kk = idx&15;
        float w = (kk < kval && n < nval) ? W[n*ws + col0 + kk] : 0.f;
        __half h = __float2half_rn(w);
        __half l = __float2half_rn(w - __half2float(h));
        uint32_t off = (uint32_t)((((n>>3)*2 + (kk>>3))<<7) + (n&7)*16 + (kk&7)*2);
        *(__half*)(dhi+off) = h; *(__half*)(dlo+off) = l;
    }
}

struct MainParams {
    const float* pts; const float* dirs;
    const float* bias[10];           // bb0..7, brm, br0
    const float* Wsig; const float* bsig;
    const float* Wr1;  const float* br1;
    float* out; int N;
};

__device__ __forceinline__ float embed_val(const float* base, int g0, int m, int k){
    if (k < 3) return base[(g0+m)*3+k];
    int q = k-3, f = q/6, rr = q - f*6, d = rr%3;
    float x = base[(g0+m)*3+d] * (float)(1<<f);
    return (rr < 3) ? sinf(x) : cosf(x);
}
__device__ __forceinline__ void store_a(unsigned char* smem, int m, int col, float v){
    uint32_t off = (uint32_t)((((m>>3)*40 + (col>>3))<<7) + (m&7)*16 + (col&7)*2);
    *(__half*)(smem+SM_A+off) = __float2half_rn(v);
}
__device__ __forceinline__ float read_a(const unsigned char* smem, int m, int k){
    uint32_t off = (uint32_t)((((m>>3)*40 + (k>>3))<<7) + (m&7)*16 + (k&7)*2);
    return __half2float(*(const __half*)(smem+SM_A+off));
}

__global__ void __launch_bounds__(512,1) nerf_mma(MainParams P)
{
    extern __shared__ __align__(1024) unsigned char smem[];
    const uint32_t sb = smem_u32(smem), mb = sb + SM_MBAR;
    float* biasS = (float*)(smem+SM_BIAS);
    float* WsigS = (float*)(smem+SM_WSIG);
    float* Wr1S  = (float*)(smem+SM_WR1);
    float* scalS = (float*)(smem+SM_SCAL);
    const int tid = threadIdx.x, lane = tid&31, wid = tid>>5;
    const int ms = wid&3, ns = wid>>2;
    const int gp0 = blockIdx.x*128;
    const long long N = P.N;

    if (tid == 0){ MB_INIT(mb,1); MB_INIT(mb+8,1); MB_INIT(mb+16,1); MB_INIT(mb+24,1); }
    __syncthreads();
    if (tid == 0){
        #pragma unroll
        for (int b = 0; b < 4; b++){
            MB_EXTX(mb + 8*b, 16384);
            bulk_g2s(sb + SM_W + b*16384, g_ws + (long long)b*16384, 16384, mb + 8*b);
        }
    }
    // zero A plane
    for (int i = tid*16; i < 81920; i += 512*16) *(uint4*)(smem+i) = make_uint4(0,0,0,0);
    for (int i = tid; i < 2048; i += 512){ int l = i>>8; biasS[i] = P.bias[l][i&255]; }
    for (int i = tid; i < 256; i += 512) biasS[2048+i] = P.bias[8][i];
    for (int i = tid; i < 256; i += 512) biasS[2304+i] = (i < 128) ? P.bias[9][i] : 0.f;
    for (int i = tid; i < 256; i += 512) WsigS[i] = P.Wsig[i];
    for (int i = tid; i < 384; i += 512) Wr1S[i] = P.Wr1[i];
    if (tid == 0){ scalS[0]=P.bsig[0]; scalS[1]=P.br1[0]; scalS[2]=P.br1[1]; scalS[3]=P.br1[2]; }
    __syncthreads();
    for (int idx = tid; idx < 128*63; idx += 512){
        int m = idx/63, k = idx - m*63;
        store_a(smem, m, 256+k, embed_val(P.pts, gp0, m, k));
    }
    {
        float* outD = P.out + 4*N;
        for (int idx = tid; idx < 128*27; idx += 512){
            int m = idx/27, k = idx - m*27;
            outD[(long long)(gp0+m)*27 + k] = embed_val(P.dirs, gp0, m, k);
        }
    }
    __syncthreads();

    float acc[64];
    int c = 0; uint32_t phs = 0;
    #pragma unroll 1
    for (int s = 0; s < 12; s++){
        const int cnt = sg_cnt[s], akt0 = sg_akt[s], layer = sg_layer[s];
        if (sg_first[s]){
            #pragma unroll
            for (int i = 0; i < 64; i++) acc[i] = 0.f;
        }
        #pragma unroll 1
        for (int ci = 0; ci < cnt; ci++, c++){
            int buf = c & 3;
            MB_WAIT(mb + 8*buf, (phs>>buf)&1);
            phs ^= 1u << buf;
            uint32_t wb = sb + SM_W + buf*16384;
            int kt0 = akt0 + ci*2;
            uint32_t ah[2][4];
            #pragma unroll
            for (int mh = 0; mh < 2; mh++){
                uint32_t ao = sb + SM_A + (uint32_t)(
                    (((ms*4 + mh*2 + ((lane>>3)&1))*40 + kt0 + (lane>>4))<<7) + (lane&7)*16);
                LDMX4(ah[mh], ao);
            }
            #pragma unroll
            for (int g = 0; g < 4; g++){
                uint32_t bo = wb + (uint32_t)(
                    ((((ns*8 + g*2 + ((lane>>4)&1))*2 + ((lane>>3)&1))<<7) + (lane&7)*16));
                uint32_t bh[4], bl[4];
                LDMX4(bh, bo);
                LDMX4(bl, bo + 8192);
                #pragma unroll
                for (int h2 = 0; h2 < 2; h2++)
                    #pragma unroll
                    for (int mh = 0; mh < 2; mh++){
                        float* a4 = acc + ((g*2+h2)*2 + mh)*4;
                        MMA16816(a4, ah[mh], bh[2*h2], bh[2*h2+1]);
                    }
                #pragma unroll
                for (int h2 = 0; h2 < 2; h2++)
                    #pragma unroll
                    for (int mh = 0; mh < 2; mh++){
                        float* a4 = acc + ((g*2+h2)*2 + mh)*4;
                        MMA16816(a4, ah[mh], bl[2*h2], bl[2*h2+1]);
                    }
            }
            __syncthreads();
            if (tid == 0 && c+4 < NCHUNK){
                MB_EXTX(mb + 8*buf, 16384);
                bulk_g2s(wb, g_ws + (long long)(c+4)*16384, 16384, mb + 8*buf);
            }
        }
        if (sg_end[s]){
            const float* bp = biasS + ((layer <= 7) ? layer*256 : (layer == 8 ? 2048 : 2304));
            #pragma unroll
            for (int nti = 0; nti < 8; nti++)
                #pragma unroll
                for (int mh = 0; mh < 2; mh++){
                    float* a4 = acc + (nti*2 + mh)*4;
                    int n0 = ns*64 + nti*8 + (lane&3)*2;
                    int mr = ms*32 + mh*16 + (lane>>2);
                    float b0 = bp[n0], b1 = bp[n0+1];
                    int ktw = ns*8 + nti;
                    float v0 = fmaxf(a4[0]+b0,0.f), v1 = fmaxf(a4[1]+b1,0.f);
                    float v2 = fmaxf(a4[2]+b0,0.f), v3 = fmaxf(a4[3]+b1,0.f);
                    uint32_t o0 = (uint32_t)((((mr>>3)*40 + ktw)<<7) + (mr&7)*16 + (lane&3)*4);
                    int m2 = mr + 8;
                    uint32_t o1 = (uint32_t)((((m2>>3)*40 + ktw)<<7) + (m2&7)*16 + (lane&3)*4);
                    *(uint32_t*)(smem+SM_A+o0) = packh2(v0, v1);
                    *(uint32_t*)(smem+SM_A+o1) = packh2(v2, v3);
                }
            if (layer == 5){
                for (int idx = tid; idx < 128*27; idx += 512){
                    int m = idx/27, k = idx - m*27;
                    store_a(smem, m, 256+k, embed_val(P.dirs, gp0, m, k));
                }
            }
            __syncthreads();
            if (layer == 7 && tid < 128){
                int m = tid; float ssum = scalS[0];
                #pragma unroll 8
                for (int k = 0; k < 256; k++) ssum = fmaf(read_a(smem, m, k), WsigS[k], ssum);
                P.out[3*N + gp0 + m] = ssum;
            }
            if (layer == 9 && tid < 128){
                int m = tid; float r0 = scalS[1], r1 = scalS[2], r2 = scalS[3];
                #pragma unroll 8
                for (int k = 0; k < 128; k++){
                    float av = read_a(smem, m, k);
                    r0 = fmaf(av, Wr1S[k], r0);
                    r1 = fmaf(av, Wr1S[128+k], r1);
                    r2 = fmaf(av, Wr1S[256+k], r2);
                }
                long long gm = gp0 + m;
                P.out[gm*3+0] = 1.f/(1.f + expf(-r0));
                P.out[gm*3+1] = 1.f/(1.f + expf(-r1));
                P.out[gm*3+2] = 1.f/(1.f + expf(-r2));
            }
        }
    }
}

extern "C" void kernel_launch(void* const* d_in, const int* in_sizes, int n_in,
                              void* d_out, int out_size)
{
    PrepParams pp;
    for (int i = 0; i < 8; i++) pp.w[i] = (const float*)d_in[2 + 2*i];
    pp.w[8] = (const float*)d_in[20];
    pp.w[9] = (const float*)d_in[22];

    MainParams mp;
    mp.pts  = (const float*)d_in[0];
    mp.dirs = (const float*)d_in[1];
    for (int i = 0; i < 8; i++) mp.bias[i] = (const float*)d_in[3 + 2*i];
    mp.bias[8] = (const float*)d_in[21];     // brm
    mp.bias[9] = (const float*)d_in[23];     // br0
    mp.Wsig = (const float*)d_in[18]; mp.bsig = (const float*)d_in[19];
    mp.Wr1  = (const float*)d_in[24]; mp.br1  = (const float*)d_in[25];
    mp.out  = (float*)d_out;
    mp.N    = in_sizes[0] / 3;

    prep<<<NCHUNK, 256>>>(pp);
    cudaFuncSetAttribute(nerf_mma, cudaFuncAttributeMaxDynamicSharedMemorySize, SM_TOTAL);
    nerf_mma<<<mp.N/128, 512, SM_TOTAL>>>(mp);
}

// round 11
// speedup vs baseline: 10.1469x; 1.0520x over previous
#include <cuda_runtime.h>
#include <cuda_fp16.h>
#include <cstdint>
#include <math.h>

#define NCHUNK 154
#define SM_A    0
#define SM_W    81920
#define SM_BIAS 147456
#define SM_WSIG 157696
#define SM_WR1  158720
#define SM_SCAL 160256
#define SM_MBAR 160272
#define SM_TOTAL 160384

__device__ __forceinline__ uint32_t smem_u32(const void* p){
    uint32_t a; asm("{ .reg .u64 t; cvta.to.shared.u64 t, %1; cvt.u32.u64 %0, t; }" : "=r"(a) : "l"(p)); return a;
}
#define MB_INIT(m,c) asm volatile("mbarrier.init.shared.b64 [%0], %1;" :: "r"(m), "r"((uint32_t)(c)) : "memory")
#define MB_EXTX(m,b) asm volatile("mbarrier.arrive.expect_tx.shared.b64 _, [%0], %1;" :: "r"(m), "r"((uint32_t)(b)) : "memory")
#define MB_ARR(m)    asm volatile("mbarrier.arrive.shared.b64 _, [%0];" :: "r"(m) : "memory")
#define MB_WAIT(m,ph) do{ uint32_t _m=(m),_p=(ph),_d; \
    asm volatile("{\n\t.reg .pred p;\n\tmbarrier.try_wait.parity.acquire.cta.shared::cta.b64 p, [%1], %2;\n\tselp.b32 %0,1,0,p;\n\t}" : "=r"(_d) : "r"(_m), "r"(_p) : "memory"); \
    if(!_d){ asm volatile("{\n\t.reg .pred P1;\n\tWL_%=:\n\tmbarrier.try_wait.parity.acquire.cta.shared::cta.b64 P1, [%0], %1, 0x989680;\n\t@P1 bra.uni WD_%=;\n\tbra.uni WL_%=;\n\tWD_%=:\n\t}" :: "r"(_m), "r"(_p) : "memory"); } }while(0)
__device__ __forceinline__ void bulk_g2s(uint32_t dst, const void* src, uint32_t bytes, uint32_t mbar){
    asm volatile("cp.async.bulk.shared::cluster.global.mbarrier::complete_tx::bytes [%0], [%1], %2, [%3];"
        :: "r"(dst), "l"(src), "r"(bytes), "r"(mbar) : "memory");
}
#define LDMX4(r,a) asm volatile("ldmatrix.sync.aligned.m8n8.x4.shared.b16 {%0,%1,%2,%3}, [%4];" \
    : "=r"((r)[0]),"=r"((r)[1]),"=r"((r)[2]),"=r"((r)[3]) : "r"(a))
#define MMA16816(c,a,b0,b1) asm volatile( \
    "mma.sync.aligned.m16n8k16.row.col.f32.f16.f16.f32 {%0,%1,%2,%3},{%4,%5,%6,%7},{%8,%9},{%0,%1,%2,%3};" \
    : "+f"((c)[0]),"+f"((c)[1]),"+f"((c)[2]),"+f"((c)[3]) \
    : "r"((a)[0]),"r"((a)[1]),"r"((a)[2]),"r"((a)[3]), "r"(b0),"r"(b1))

__device__ __forceinline__ uint32_t packh2(float v0, float v1){
    __half2 h = __floats2half2_rn(v0, v1);
    return *reinterpret_cast<uint32_t*>(&h);
}

// segment tables: 12 segments over 10 GEMM layers, k16 chunks
__constant__ unsigned char sg_layer[12]={0,1,2,3,4,5,5,6,7,8,9,9};
__constant__ short sg_cnt[12]={4,16,16,16,16,4,16,16,16,16,16,2};
__constant__ short sg_cum[12]={0,4,20,36,52,68,72,88,104,120,136,152};
__constant__ unsigned char sg_akt[12]={32,0,0,0,0,32,0,0,0,0,0,32};
__constant__ unsigned char sg_first[12]={1,1,1,1,1,1,0,1,1,1,1,0};
__constant__ unsigned char sg_end[12]={1,1,1,1,1,0,1,1,1,1,0,1};
__constant__ unsigned char sg_w[12]={0,1,2,3,4,5,5,6,7,8,9,9};
__constant__ short sg_wcol[12]={0,0,0,0,0,0,63,0,0,0,0,256};
__constant__ short sg_kmax[12]={63,256,256,256,256,63,256,256,256,256,256,27};
__constant__ short sg_wstr[12]={63,256,256,256,256,319,319,256,256,256,283,283};
__constant__ short sg_nval[12]={256,256,256,256,256,256,256,256,256,256,128,128};

__device__ __align__(1024) unsigned char g_ws[NCHUNK*16384];

struct PrepParams { const float* w[10]; };
__global__ void prep(PrepParams pp){
    int c = blockIdx.x, s = 11;
    for (int i = 1; i < 12; i++) if (c < sg_cum[i]){ s = i-1; break; }
    int ci = c - sg_cum[s];
    const float* W = pp.w[sg_w[s]];
    int kval = sg_kmax[s] - 16*ci; if (kval > 16) kval = 16;
    int nval = sg_nval[s], ws = sg_wstr[s], col0 = sg_wcol[s] + ci*16;
    unsigned char* dhi = g_ws + (long long)c*16384;
    unsigned char* dlo = dhi + 8192;
    for (int idx = threadIdx.x; idx < 4096; idx += blockDim.x){
        int n = idx>>4, kk = idx&15;
        float w = (kk < kval && n < nval) ? W[n*ws + col0 + kk] : 0.f;
        __half h = __float2half_rn(w);
        __half l = __float2half_rn(w - __half2float(h));
        uint32_t off = (uint32_t)((((n>>3)*2 + (kk>>3))<<7) + (n&7)*16 + (kk&7)*2);
        *(__half*)(dhi+off) = h; *(__half*)(dlo+off) = l;
    }
}

struct MainParams {
    const float* pts; const float* dirs;
    const float* bias[10];           // bb0..7, brm, br0
    const float* Wsig; const float* bsig;
    const float* Wr1;  const float* br1;
    float* out; int N;
};

__device__ __forceinline__ float embed_val(const float* base, int g0, int m, int k){
    if (k < 3) return base[(g0+m)*3+k];
    int q = k-3, f = q/6, rr = q - f*6, d = rr%3;
    float x = base[(g0+m)*3+d] * (float)(1<<f);
    return (rr < 3) ? sinf(x) : cosf(x);
}
__device__ __forceinline__ void store_a(unsigned char* smem, int m, int col, float v){
    uint32_t off = (uint32_t)((((m>>3)*40 + (col>>3))<<7) + (m&7)*16 + (col&7)*2);
    *(__half*)(smem+SM_A+off) = __float2half_rn(v);
}
__device__ __forceinline__ float read_a(const unsigned char* smem, int m, int k){
    uint32_t off = (uint32_t)((((m>>3)*40 + (k>>3))<<7) + (m&7)*16 + (k&7)*2);
    return __half2float(*(const __half*)(smem+SM_A+off));
}

__global__ void __launch_bounds__(512,1) nerf_mma(MainParams P)
{
    extern __shared__ __align__(1024) unsigned char smem[];
    const uint32_t sb = smem_u32(smem), mb = sb + SM_MBAR;
    // mb+0..24: full[0..3]   mb+32..56: cons[0..3]
    float* biasS = (float*)(smem+SM_BIAS);
    float* WsigS = (float*)(smem+SM_WSIG);
    float* Wr1S  = (float*)(smem+SM_WR1);
    float* scalS = (float*)(smem+SM_SCAL);
    const int tid = threadIdx.x, lane = tid&31, wid = tid>>5;
    const int ms = wid&3, ns = wid>>2;
    const int gp0 = blockIdx.x*128;
    const long long N = P.N;

    if (tid == 0){
        MB_INIT(mb,1); MB_INIT(mb+8,1); MB_INIT(mb+16,1); MB_INIT(mb+24,1);
        MB_INIT(mb+32,16); MB_INIT(mb+40,16); MB_INIT(mb+48,16); MB_INIT(mb+56,16);
    }
    __syncthreads();
    if (tid == 0){
        #pragma unroll
        for (int b = 0; b < 4; b++){
            MB_EXTX(mb + 8*b, 16384);
            bulk_g2s(sb + SM_W + b*16384, g_ws + (long long)b*16384, 16384, mb + 8*b);
        }
    }
    // zero A plane
    for (int i = tid*16; i < 81920; i += 512*16) *(uint4*)(smem+i) = make_uint4(0,0,0,0);
    for (int i = tid; i < 2048; i += 512){ int l = i>>8; biasS[i] = P.bias[l][i&255]; }
    for (int i = tid; i < 256; i += 512) biasS[2048+i] = P.bias[8][i];
    for (int i = tid; i < 256; i += 512) biasS[2304+i] = (i < 128) ? P.bias[9][i] : 0.f;
    for (int i = tid; i < 256; i += 512) WsigS[i] = P.Wsig[i];
    for (int i = tid; i < 384; i += 512) Wr1S[i] = P.Wr1[i];
    if (tid == 0){ scalS[0]=P.bsig[0]; scalS[1]=P.br1[0]; scalS[2]=P.br1[1]; scalS[3]=P.br1[2]; }
    __syncthreads();
    for (int idx = tid; idx < 128*63; idx += 512){
        int m = idx/63, k = idx - m*63;
        store_a(smem, m, 256+k, embed_val(P.pts, gp0, m, k));
    }
    {
        float* outD = P.out + 4*N;
        for (int idx = tid; idx < 128*27; idx += 512){
            int m = idx/27, k = idx - m*27;
            outD[(long long)(gp0+m)*27 + k] = embed_val(P.dirs, gp0, m, k);
        }
    }
    __syncthreads();

    float acc[64];
    int c = 0; uint32_t phs = 0, cphs = 0;
    #pragma unroll 1
    for (int s = 0; s < 12; s++){
        const int cnt = sg_cnt[s], akt0 = sg_akt[s], layer = sg_layer[s];
        if (sg_first[s]){
            #pragma unroll
            for (int i = 0; i < 64; i++) acc[i] = 0.f;
        }
        #pragma unroll 1
        for (int ci = 0; ci < cnt; ci++, c++){
            int buf = c & 3;
            MB_WAIT(mb + 8*buf, (phs>>buf)&1);
            phs ^= 1u << buf;
            uint32_t wb = sb + SM_W + buf*16384;
            int kt0 = akt0 + ci*2;
            uint32_t ah[2][4];
            #pragma unroll
            for (int mh = 0; mh < 2; mh++){
                uint32_t ao = sb + SM_A + (uint32_t)(
                    (((ms*4 + mh*2 + ((lane>>3)&1))*40 + kt0 + (lane>>4))<<7) + (lane&7)*16);
                LDMX4(ah[mh], ao);
            }
            #pragma unroll
            for (int g = 0; g < 4; g++){
                uint32_t bo = wb + (uint32_t)(
                    ((((ns*8 + g*2 + ((lane>>4)&1))*2 + ((lane>>3)&1))<<7) + (lane&7)*16));
                uint32_t bh[4], bl[4];
                LDMX4(bh, bo);
                LDMX4(bl, bo + 8192);
                #pragma unroll
                for (int h2 = 0; h2 < 2; h2++)
                    #pragma unroll
                    for (int mh = 0; mh < 2; mh++){
                        float* a4 = acc + ((g*2+h2)*2 + mh)*4;
                        MMA16816(a4, ah[mh], bh[2*h2], bh[2*h2+1]);
                    }
                #pragma unroll
                for (int h2 = 0; h2 < 2; h2++)
                    #pragma unroll
                    for (int mh = 0; mh < 2; mh++){
                        float* a4 = acc + ((g*2+h2)*2 + mh)*4;
                        MMA16816(a4, ah[mh], bl[2*h2], bl[2*h2+1]);
                    }
            }
            // this warp is done reading buffer `buf`
            if (lane == 0) MB_ARR(mb + 32 + 8*buf);
            // loader: refill this buffer once ALL warps have consumed it
            if (tid == 0 && c+4 < NCHUNK){
                MB_WAIT(mb + 32 + 8*buf, (cphs>>buf)&1);
                cphs ^= 1u << buf;
                MB_EXTX(mb + 8*buf, 16384);
                bulk_g2s(wb, g_ws + (long long)(c+4)*16384, 16384, mb + 8*buf);
            }
        }
        if (sg_end[s]){
            __syncthreads();   // all warps done reading A for this layer
            const float* bp = biasS + ((layer <= 7) ? layer*256 : (layer == 8 ? 2048 : 2304));
            #pragma unroll
            for (int nti = 0; nti < 8; nti++)
                #pragma unroll
                for (int mh = 0; mh < 2; mh++){
                    float* a4 = acc + (nti*2 + mh)*4;
                    int n0 = ns*64 + nti*8 + (lane&3)*2;
                    int mr = ms*32 + mh*16 + (lane>>2);
                    float b0 = bp[n0], b1 = bp[n0+1];
                    int ktw = ns*8 + nti;
                    float v0 = fmaxf(a4[0]+b0,0.f), v1 = fmaxf(a4[1]+b1,0.f);
                    float v2 = fmaxf(a4[2]+b0,0.f), v3 = fmaxf(a4[3]+b1,0.f);
                    uint32_t o0 = (uint32_t)((((mr>>3)*40 + ktw)<<7) + (mr&7)*16 + (lane&3)*4);
                    int m2 = mr + 8;
                    uint32_t o1 = (uint32_t)((((m2>>3)*40 + ktw)<<7) + (m2&7)*16 + (lane&3)*4);
                    *(uint32_t*)(smem+SM_A+o0) = packh2(v0, v1);
                    *(uint32_t*)(smem+SM_A+o1) = packh2(v2, v3);
                }
            if (layer == 5){
                for (int idx = tid; idx < 128*27; idx += 512){
                    int m = idx/27, k = idx - m*27;
                    store_a(smem, m, 256+k, embed_val(P.dirs, gp0, m, k));
                }
            }
            __syncthreads();
            if (layer == 7 && tid < 128){
                int m = tid; float ssum = scalS[0];
                #pragma unroll 8
                for (int k = 0; k < 256; k++) ssum = fmaf(read_a(smem, m, k), WsigS[k], ssum);
                P.out[3*N + gp0 + m] = ssum;
            }
            if (layer == 9 && tid < 128){
                int m = tid; float r0 = scalS[1], r1 = scalS[2], r2 = scalS[3];
                #pragma unroll 8
                for (int k = 0; k < 128; k++){
                    float av = read_a(smem, m, k);
                    r0 = fmaf(av, Wr1S[k], r0);
                    r1 = fmaf(av, Wr1S[128+k], r1);
                    r2 = fmaf(av, Wr1S[256+k], r2);
                }
                long long gm = gp0 + m;
                P.out[gm*3+0] = 1.f/(1.f + expf(-r0));
                P.out[gm*3+1] = 1.f/(1.f + expf(-r1));
                P.out[gm*3+2] = 1.f/(1.f + expf(-r2));
            }
        }
    }
}

extern "C" void kernel_launch(void* const* d_in, const int* in_sizes, int n_in,
                              void* d_out, int out_size)
{
    PrepParams pp;
    for (int i = 0; i < 8; i++) pp.w[i] = (const float*)d_in[2 + 2*i];
    pp.w[8] = (const float*)d_in[20];
    pp.w[9] = (const float*)d_in[22];

    MainParams mp;
    mp.pts  = (const float*)d_in[0];
    mp.dirs = (const float*)d_in[1];
    for (int i = 0; i < 8; i++) mp.bias[i] = (const float*)d_in[3 + 2*i];
    mp.bias[8] = (const float*)d_in[21];     // brm
    mp.bias[9] = (const float*)d_in[23];     // br0
    mp.Wsig = (const float*)d_in[18]; mp.bsig = (const float*)d_in[19];
    mp.Wr1  = (const float*)d_in[24]; mp.br1  = (const float*)d_in[25];
    mp.out  = (float*)d_out;
    mp.N    = in_sizes[0] / 3;

    prep<<<NCHUNK, 256>>>(pp);
    cudaFuncSetAttribute(nerf_mma, cudaFuncAttributeMaxDynamicSharedMemorySize, SM_TOTAL);
    nerf_mma<<<mp.N/128, 512, SM_TOTAL>>>(mp);
}

// round 12
// speedup vs baseline: 10.4841x; 1.0332x over previous
#include <cuda_runtime.h>
#include <cuda_fp16.h>
#include <cstdint>
#include <math.h>

#define NCHUNK 154
#define SM_A    0
#define SM_W    40960
#define SM_MBAR 106496
#define SM_TOTAL 106624

__device__ __forceinline__ uint32_t smem_u32(const void* p){
    uint32_t a; asm("{ .reg .u64 t; cvta.to.shared.u64 t, %1; cvt.u32.u64 %0, t; }" : "=r"(a) : "l"(p)); return a;
}
#define MB_INIT(m,c) asm volatile("mbarrier.init.shared.b64 [%0], %1;" :: "r"(m), "r"((uint32_t)(c)) : "memory")
#define MB_EXTX(m,b) asm volatile("mbarrier.arrive.expect_tx.shared.b64 _, [%0], %1;" :: "r"(m), "r"((uint32_t)(b)) : "memory")
#define MB_ARR(m)    asm volatile("mbarrier.arrive.shared.b64 _, [%0];" :: "r"(m) : "memory")
#define MB_WAIT(m,ph) do{ uint32_t _m=(m),_p=(ph),_d; \
    asm volatile("{\n\t.reg .pred p;\n\tmbarrier.try_wait.parity.acquire.cta.shared::cta.b64 p, [%1], %2;\n\tselp.b32 %0,1,0,p;\n\t}" : "=r"(_d) : "r"(_m), "r"(_p) : "memory"); \
    if(!_d){ asm volatile("{\n\t.reg .pred P1;\n\tWL_%=:\n\tmbarrier.try_wait.parity.acquire.cta.shared::cta.b64 P1, [%0], %1, 0x989680;\n\t@P1 bra.uni WD_%=;\n\tbra.uni WL_%=;\n\tWD_%=:\n\t}" :: "r"(_m), "r"(_p) : "memory"); } }while(0)
__device__ __forceinline__ void bulk_g2s(uint32_t dst, const void* src, uint32_t bytes, uint32_t mbar){
    asm volatile("cp.async.bulk.shared::cluster.global.mbarrier::complete_tx::bytes [%0], [%1], %2, [%3];"
        :: "r"(dst), "l"(src), "r"(bytes), "r"(mbar) : "memory");
}
#define LDMX4(r,a) asm volatile("ldmatrix.sync.aligned.m8n8.x4.shared.b16 {%0,%1,%2,%3}, [%4];" \
    : "=r"((r)[0]),"=r"((r)[1]),"=r"((r)[2]),"=r"((r)[3]) : "r"(a))
#define MMA16816(c,a,b0,b1) asm volatile( \
    "mma.sync.aligned.m16n8k16.row.col.f32.f16.f16.f32 {%0,%1,%2,%3},{%4,%5,%6,%7},{%8,%9},{%0,%1,%2,%3};" \
    : "+f"((c)[0]),"+f"((c)[1]),"+f"((c)[2]),"+f"((c)[3]) \
    : "r"((a)[0]),"r"((a)[1]),"r"((a)[2]),"r"((a)[3]), "r"(b0),"r"(b1))

__device__ __forceinline__ uint32_t packh2(float v0, float v1){
    __half2 h = __floats2half2_rn(v0, v1);
    return *reinterpret_cast<uint32_t*>(&h);
}

// segment tables: 12 segments over 10 GEMM layers, k16 chunks
__constant__ unsigned char sg_layer[12]={0,1,2,3,4,5,5,6,7,8,9,9};
__constant__ short sg_cnt[12]={4,16,16,16,16,4,16,16,16,16,16,2};
__constant__ short sg_cum[12]={0,4,20,36,52,68,72,88,104,120,136,152};
__constant__ unsigned char sg_akt[12]={32,0,0,0,0,32,0,0,0,0,0,32};
__constant__ unsigned char sg_first[12]={1,1,1,1,1,1,0,1,1,1,1,0};
__constant__ unsigned char sg_end[12]={1,1,1,1,1,0,1,1,1,1,0,1};
__constant__ unsigned char sg_w[12]={0,1,2,3,4,5,5,6,7,8,9,9};
__constant__ short sg_wcol[12]={0,0,0,0,0,0,63,0,0,0,0,256};
__constant__ short sg_kmax[12]={63,256,256,256,256,63,256,256,256,256,256,27};
__constant__ short sg_wstr[12]={63,256,256,256,256,319,319,256,256,256,283,283};
__constant__ short sg_nval[12]={256,256,256,256,256,256,256,256,256,256,128,128};

__device__ __align__(1024) unsigned char g_ws[NCHUNK*16384];

struct PrepParams { const float* w[10]; };
__global__ void prep(PrepParams pp){
    int c = blockIdx.x, s = 11;
    for (int i = 1; i < 12; i++) if (c < sg_cum[i]){ s = i-1; break; }
    int ci = c - sg_cum[s];
    const float* W = pp.w[sg_w[s]];
    int kval = sg_kmax[s] - 16*ci; if (kval > 16) kval = 16;
    int nval = sg_nval[s], ws = sg_wstr[s], col0 = sg_wcol[s] + ci*16;
    unsigned char* dhi = g_ws + (long long)c*16384;
    unsigned char* dlo = dhi + 8192;
    for (int idx = threadIdx.x; idx < 4096; idx += blockDim.x){
        int n = idx>>4, kk = idx&15;
        float w = (kk < kval && n < nval) ? W[n*ws + col0 + kk] : 0.f;
        __half h = __float2half_rn(w);
        __half l = __float2half_rn(w - __half2float(h));
        uint32_t off = (uint32_t)((((n>>3)*2 + (kk>>3))<<7) + (n&7)*16 + (kk&7)*2);
        *(__half*)(dhi+off) = h; *(__half*)(dlo+off) = l;
    }
}

struct MainParams {
    const float* pts; const float* dirs;
    const float* bias[10];           // bb0..7, brm, br0
    const float* Wsig; const float* bsig;
    const float* Wr1;  const float* br1;
    float* out; int N;
};

__device__ __forceinline__ float embed_val(const float* base, int g0, int m, int k){
    if (k < 3) return base[(g0+m)*3+k];
    int q = k-3, f = q/6, rr = q - f*6, d = rr%3;
    float x = base[(g0+m)*3+d] * (float)(1<<f);
    return (rr < 3) ? sinf(x) : cosf(x);
}
__device__ __forceinline__ void store_a(unsigned char* smem, int m, int col, float v){
    uint32_t off = (uint32_t)((((m>>3)*40 + (col>>3))<<7) + (m&7)*16 + (col&7)*2);
    *(__half*)(smem+SM_A+off) = __float2half_rn(v);
}
__device__ __forceinline__ float read_a(const unsigned char* smem, int m, int k){
    uint32_t off = (uint32_t)((((m>>3)*40 + (k>>3))<<7) + (m&7)*16 + (k&7)*2);
    return __half2float(*(const __half*)(smem+SM_A+off));
}

__global__ void __launch_bounds__(256,2) nerf_mma(MainParams P)
{
    extern __shared__ __align__(1024) unsigned char smem[];
    const uint32_t sb = smem_u32(smem), mb = sb + SM_MBAR;
    // mb+0..24: full[0..3]   mb+32..56: cons[0..3] (count 8)
    const int tid = threadIdx.x, lane = tid&31, wid = tid>>5;
    const int ms = wid&1, ns = wid>>1;       // 2 m-blocks x 4 n-blocks
    const int gp0 = blockIdx.x*64;
    const long long N = P.N;

    if (tid == 0){
        MB_INIT(mb,1); MB_INIT(mb+8,1); MB_INIT(mb+16,1); MB_INIT(mb+24,1);
        MB_INIT(mb+32,8); MB_INIT(mb+40,8); MB_INIT(mb+48,8); MB_INIT(mb+56,8);
    }
    __syncthreads();
    if (tid == 0){
        #pragma unroll
        for (int b = 0; b < 4; b++){
            MB_EXTX(mb + 8*b, 16384);
            bulk_g2s(sb + SM_W + b*16384, g_ws + (long long)b*16384, 16384, mb + 8*b);
        }
    }
    // zero A plane (40960 B)
    for (int i = tid*16; i < 40960; i += 256*16) *(uint4*)(smem+i) = make_uint4(0,0,0,0);
    __syncthreads();
    for (int idx = tid; idx < 64*63; idx += 256){
        int m = idx/63, k = idx - m*63;
        store_a(smem, m, 256+k, embed_val(P.pts, gp0, m, k));
    }
    {
        float* outD = P.out + 4*N;
        for (int idx = tid; idx < 64*27; idx += 256){
            int m = idx/27, k = idx - m*27;
            outD[(long long)(gp0+m)*27 + k] = embed_val(P.dirs, gp0, m, k);
        }
    }
    __syncthreads();

    float acc[64];
    int c = 0; uint32_t phs = 0, cphs = 0;
    #pragma unroll 1
    for (int s = 0; s < 12; s++){
        const int cnt = sg_cnt[s], akt0 = sg_akt[s], layer = sg_layer[s];
        if (sg_first[s]){
            #pragma unroll
            for (int i = 0; i < 64; i++) acc[i] = 0.f;
        }
        #pragma unroll 1
        for (int ci = 0; ci < cnt; ci++, c++){
            int buf = c & 3;
            MB_WAIT(mb + 8*buf, (phs>>buf)&1);
            phs ^= 1u << buf;
            uint32_t wb = sb + SM_W + buf*16384;
            int kt0 = akt0 + ci*2;
            uint32_t ah[2][4];
            #pragma unroll
            for (int mh = 0; mh < 2; mh++){
                uint32_t ao = sb + SM_A + (uint32_t)(
                    (((ms*4 + mh*2 + ((lane>>3)&1))*40 + kt0 + (lane>>4))<<7) + (lane&7)*16);
                LDMX4(ah[mh], ao);
            }
            #pragma unroll
            for (int g = 0; g < 4; g++){
                uint32_t bo = wb + (uint32_t)(
                    ((((ns*8 + g*2 + ((lane>>4)&1))*2 + ((lane>>3)&1))<<7) + (lane&7)*16));
                uint32_t bh[4], bl[4];
                LDMX4(bh, bo);
                LDMX4(bl, bo + 8192);
                #pragma unroll
                for (int h2 = 0; h2 < 2; h2++)
                    #pragma unroll
                    for (int mh = 0; mh < 2; mh++){
                        float* a4 = acc + ((g*2+h2)*2 + mh)*4;
                        MMA16816(a4, ah[mh], bh[2*h2], bh[2*h2+1]);
                    }
                #pragma unroll
                for (int h2 = 0; h2 < 2; h2++)
                    #pragma unroll
                    for (int mh = 0; mh < 2; mh++){
                        float* a4 = acc + ((g*2+h2)*2 + mh)*4;
                        MMA16816(a4, ah[mh], bl[2*h2], bl[2*h2+1]);
                    }
            }
            if (lane == 0) MB_ARR(mb + 32 + 8*buf);
            if (tid == 0 && c+4 < NCHUNK){
                MB_WAIT(mb + 32 + 8*buf, (cphs>>buf)&1);
                cphs ^= 1u << buf;
                MB_EXTX(mb + 8*buf, 16384);
                bulk_g2s(wb, g_ws + (long long)(c+4)*16384, 16384, mb + 8*buf);
            }
        }
        if (sg_end[s]){
            __syncthreads();   // all warps done reading A for this layer
            const float* bp = P.bias[layer];
            const int nmax = (layer == 9) ? 128 : 256;
            #pragma unroll
            for (int nti = 0; nti < 8; nti++)
                #pragma unroll
                for (int mh = 0; mh < 2; mh++){
                    float* a4 = acc + (nti*2 + mh)*4;
                    int n0 = ns*64 + nti*8 + (lane&3)*2;
                    int mr = ms*32 + mh*16 + (lane>>2);
                    float b0 = (n0 < nmax) ? __ldg(bp + n0) : 0.f;
                    float b1 = (n0+1 < nmax) ? __ldg(bp + n0 + 1) : 0.f;
                    int ktw = ns*8 + nti;
                    float v0 = fmaxf(a4[0]+b0,0.f), v1 = fmaxf(a4[1]+b1,0.f);
                    float v2 = fmaxf(a4[2]+b0,0.f), v3 = fmaxf(a4[3]+b1,0.f);
                    uint32_t o0 = (uint32_t)((((mr>>3)*40 + ktw)<<7) + (mr&7)*16 + (lane&3)*4);
                    int m2 = mr + 8;
                    uint32_t o1 = (uint32_t)((((m2>>3)*40 + ktw)<<7) + (m2&7)*16 + (lane&3)*4);
                    *(uint32_t*)(smem+SM_A+o0) = packh2(v0, v1);
                    *(uint32_t*)(smem+SM_A+o1) = packh2(v2, v3);
                }
            if (layer == 5){
                for (int idx = tid; idx < 64*27; idx += 256){
                    int m = idx/27, k = idx - m*27;
                    store_a(smem, m, 256+k, embed_val(P.dirs, gp0, m, k));
                }
            }
            __syncthreads();
            if (layer == 7 && tid < 64){
                int m = tid; float ssum = __ldg(P.bsig);
                #pragma unroll 8
                for (int k = 0; k < 256; k++) ssum = fmaf(read_a(smem, m, k), __ldg(P.Wsig + k), ssum);
                P.out[3*N + gp0 + m] = ssum;
            }
            if (layer == 9 && tid < 64){
                int m = tid;
                float r0 = __ldg(P.br1+0), r1 = __ldg(P.br1+1), r2 = __ldg(P.br1+2);
                #pragma unroll 8
                for (int k = 0; k < 128; k++){
                    float av = read_a(smem, m, k);
                    r0 = fmaf(av, __ldg(P.Wr1 + k), r0);
                    r1 = fmaf(av, __ldg(P.Wr1 + 128 + k), r1);
                    r2 = fmaf(av, __ldg(P.Wr1 + 256 + k), r2);
                }
                long long gm = gp0 + m;
                P.out[gm*3+0] = 1.f/(1.f + expf(-r0));
                P.out[gm*3+1] = 1.f/(1.f + expf(-r1));
                P.out[gm*3+2] = 1.f/(1.f + expf(-r2));
            }
        }
    }
}

extern "C" void kernel_launch(void* const* d_in, const int* in_sizes, int n_in,
                              void* d_out, int out_size)
{
    PrepParams pp;
    for (int i = 0; i < 8; i++) pp.w[i] = (const float*)d_in[2 + 2*i];
    pp.w[8] = (const float*)d_in[20];
    pp.w[9] = (const float*)d_in[22];

    MainParams mp;
    mp.pts  = (const float*)d_in[0];
    mp.dirs = (const float*)d_in[1];
    for (int i = 0; i < 8; i++) mp.bias[i] = (const float*)d_in[3 + 2*i];
    mp.bias[8] = (const float*)d_in[21];     // brm
    mp.bias[9] = (const float*)d_in[23];     // br0
    mp.Wsig = (const float*)d_in[18]; mp.bsig = (const float*)d_in[19];
    mp.Wr1  = (const float*)d_in[24]; mp.br1  = (const float*)d_in[25];
    mp.out  = (float*)d_out;
    mp.N    = in_sizes[0] / 3;

    prep<<<NCHUNK, 256>>>(pp);
    cudaFuncSetAttribute(nerf_mma, cudaFuncAttributeMaxDynamicSharedMemorySize, SM_TOTAL);
    nerf_mma<<<mp.N/64, 256, SM_TOTAL>>>(mp);
}

// round 13
// speedup vs baseline: 15.6136x; 1.4893x over previous
#include <cuda_runtime.h>
#include <cuda_fp16.h>
#include <cstdint>
#include <math.h>

#define NCHUNK 77
#define SM_A    0
#define SM_W    40960
#define SM_MBAR 106496
#define SM_TOTAL 106624

__device__ __forceinline__ uint32_t smem_u32(const void* p){
    uint32_t a; asm("{ .reg .u64 t; cvta.to.shared.u64 t, %1; cvt.u32.u64 %0, t; }" : "=r"(a) : "l"(p)); return a;
}
#define MB_INIT(m,c) asm volatile("mbarrier.init.shared.b64 [%0], %1;" :: "r"(m), "r"((uint32_t)(c)) : "memory")
#define MB_EXTX(m,b) asm volatile("mbarrier.arrive.expect_tx.shared.b64 _, [%0], %1;" :: "r"(m), "r"((uint32_t)(b)) : "memory")
#define MB_ARR(m)    asm volatile("mbarrier.arrive.shared.b64 _, [%0];" :: "r"(m) : "memory")
#define MB_WAIT(m,ph) do{ uint32_t _m=(m),_p=(ph),_d; \
    asm volatile("{\n\t.reg .pred p;\n\tmbarrier.try_wait.parity.acquire.cta.shared::cta.b64 p, [%1], %2;\n\tselp.b32 %0,1,0,p;\n\t}" : "=r"(_d) : "r"(_m), "r"(_p) : "memory"); \
    if(!_d){ asm volatile("{\n\t.reg .pred P1;\n\tWL_%=:\n\tmbarrier.try_wait.parity.acquire.cta.shared::cta.b64 P1, [%0], %1, 0x989680;\n\t@P1 bra.uni WD_%=;\n\tbra.uni WL_%=;\n\tWD_%=:\n\t}" :: "r"(_m), "r"(_p) : "memory"); } }while(0)
__device__ __forceinline__ void bulk_g2s(uint32_t dst, const void* src, uint32_t bytes, uint32_t mbar){
    asm volatile("cp.async.bulk.shared::cluster.global.mbarrier::complete_tx::bytes [%0], [%1], %2, [%3];"
        :: "r"(dst), "l"(src), "r"(bytes), "r"(mbar) : "memory");
}
#define LDMX4(r,a) asm volatile("ldmatrix.sync.aligned.m8n8.x4.shared.b16 {%0,%1,%2,%3}, [%4];" \
    : "=r"((r)[0]),"=r"((r)[1]),"=r"((r)[2]),"=r"((r)[3]) : "r"(a))
#define MMA16816(c,a,b0,b1) asm volatile( \
    "mma.sync.aligned.m16n8k16.row.col.f32.f16.f16.f32 {%0,%1,%2,%3},{%4,%5,%6,%7},{%8,%9},{%0,%1,%2,%3};" \
    : "+f"((c)[0]),"+f"((c)[1]),"+f"((c)[2]),"+f"((c)[3]) \
    : "r"((a)[0]),"r"((a)[1]),"r"((a)[2]),"r"((a)[3]), "r"(b0),"r"(b1))

__device__ __forceinline__ uint32_t packh2(float v0, float v1){
    __half2 h = __floats2half2_rn(v0, v1);
    return *reinterpret_cast<uint32_t*>(&h);
}

// segment tables: 12 segments over 10 GEMM layers, k32 chunks
__constant__ unsigned char sg_layer[12]={0,1,2,3,4,5,5,6,7,8,9,9};
__constant__ short sg_cnt[12]={2,8,8,8,8,2,8,8,8,8,8,1};
__constant__ short sg_cum[12]={0,2,10,18,26,34,36,44,52,60,68,76};
__constant__ unsigned char sg_akt[12]={32,0,0,0,0,32,0,0,0,0,0,32};
__constant__ unsigned char sg_first[12]={1,1,1,1,1,1,0,1,1,1,1,0};
__constant__ unsigned char sg_end[12]={1,1,1,1,1,0,1,1,1,1,0,1};
__constant__ unsigned char sg_w[12]={0,1,2,3,4,5,5,6,7,8,9,9};
__constant__ short sg_wcol[12]={0,0,0,0,0,0,63,0,0,0,0,256};
__constant__ short sg_kmax[12]={63,256,256,256,256,63,256,256,256,256,256,27};
__constant__ short sg_wstr[12]={63,256,256,256,256,319,319,256,256,256,283,283};
__constant__ short sg_nval[12]={256,256,256,256,256,256,256,256,256,256,128,128};

__device__ __align__(1024) unsigned char g_ws[NCHUNK*16384];

struct PrepParams { const float* w[10]; };
__global__ void prep(PrepParams pp){
    int c = blockIdx.x, s = 11;
    for (int i = 1; i < 12; i++) if (c < sg_cum[i]){ s = i-1; break; }
    int ci = c - sg_cum[s];
    const float* W = pp.w[sg_w[s]];
    int kval = sg_kmax[s] - 32*ci; if (kval > 32) kval = 32;
    int nval = sg_nval[s], ws = sg_wstr[s], col0 = sg_wcol[s] + ci*32;
    unsigned char* dst = g_ws + (long long)c*16384;
    for (int idx = threadIdx.x; idx < 8192; idx += blockDim.x){
        int n = idx>>5, kk = idx&31;
        float w = (kk < kval && n < nval) ? W[n*ws + col0 + kk] : 0.f;
        uint32_t off = (uint32_t)((((n>>3)*4 + (kk>>3))<<7) + ((n&7)<<4) + ((kk&7)<<1));
        *(__half*)(dst+off) = __float2half_rn(w);
    }
}

struct MainParams {
    const float* pts; const float* dirs;
    const float* bias[10];           // bb0..7, brm, br0
    const float* Wsig; const float* bsig;
    const float* Wr1;  const float* br1;
    float* out; int N;
};

__device__ __forceinline__ float embed_val(const float* base, int g0, int m, int k){
    if (k < 3) return base[(g0+m)*3+k];
    int q = k-3, f = q/6, rr = q - f*6, d = rr%3;
    float x = base[(g0+m)*3+d] * (float)(1<<f);
    return (rr < 3) ? sinf(x) : cosf(x);
}
__device__ __forceinline__ void store_a(unsigned char* smem, int m, int col, float v){
    uint32_t off = (uint32_t)((((m>>3)*40 + (col>>3))<<7) + (m&7)*16 + (col&7)*2);
    *(__half*)(smem+SM_A+off) = __float2half_rn(v);
}
__device__ __forceinline__ float read_a(const unsigned char* smem, int m, int k){
    uint32_t off = (uint32_t)((((m>>3)*40 + (k>>3))<<7) + (m&7)*16 + (k&7)*2);
    return __half2float(*(const __half*)(smem+SM_A+off));
}

__global__ void __launch_bounds__(256,2) nerf_mma(MainParams P)
{
    extern __shared__ __align__(1024) unsigned char smem[];
    const uint32_t sb = smem_u32(smem), mb = sb + SM_MBAR;
    // mb+0..24: full[0..3]   mb+32..56: cons[0..3] (count 8)
    const int tid = threadIdx.x, lane = tid&31, wid = tid>>5;
    const int ms = wid&1, ns = wid>>1;       // 2 m-blocks x 4 n-blocks
    const int gp0 = blockIdx.x*64;
    const long long N = P.N;

    if (tid == 0){
        MB_INIT(mb,1); MB_INIT(mb+8,1); MB_INIT(mb+16,1); MB_INIT(mb+24,1);
        MB_INIT(mb+32,8); MB_INIT(mb+40,8); MB_INIT(mb+48,8); MB_INIT(mb+56,8);
    }
    __syncthreads();
    if (tid == 0){
        #pragma unroll
        for (int b = 0; b < 4; b++){
            MB_EXTX(mb + 8*b, 16384);
            bulk_g2s(sb + SM_W + b*16384, g_ws + (long long)b*16384, 16384, mb + 8*b);
        }
    }
    // zero A plane (40960 B)
    for (int i = tid*16; i < 40960; i += 256*16) *(uint4*)(smem+i) = make_uint4(0,0,0,0);
    __syncthreads();
    for (int idx = tid; idx < 64*63; idx += 256){
        int m = idx/63, k = idx - m*63;
        store_a(smem, m, 256+k, embed_val(P.pts, gp0, m, k));
    }
    {
        float* outD = P.out + 4*N;
        for (int idx = tid; idx < 64*27; idx += 256){
            int m = idx/27, k = idx - m*27;
            outD[(long long)(gp0+m)*27 + k] = embed_val(P.dirs, gp0, m, k);
        }
    }
    __syncthreads();

    float acc[64];
    int c = 0; uint32_t phs = 0, cphs = 0;
    #pragma unroll 1
    for (int s = 0; s < 12; s++){
        const int cnt = sg_cnt[s], akt0 = sg_akt[s], layer = sg_layer[s];
        if (sg_first[s]){
            #pragma unroll
            for (int i = 0; i < 64; i++) acc[i] = 0.f;
        }
        #pragma unroll 1
        for (int ci = 0; ci < cnt; ci++, c++){
            int buf = c & 3;
            MB_WAIT(mb + 8*buf, (phs>>buf)&1);
            phs ^= 1u << buf;
            uint32_t wb = sb + SM_W + buf*16384;
            int kt0 = akt0 + ci*4;
            #pragma unroll
            for (int kh = 0; kh < 2; kh++){
                uint32_t ah[2][4];
                #pragma unroll
                for (int mh = 0; mh < 2; mh++){
                    uint32_t ao = sb + SM_A + (uint32_t)(
                        (((ms*4 + mh*2 + ((lane>>3)&1))*40 + kt0 + 2*kh + (lane>>4))<<7) + (lane&7)*16);
                    LDMX4(ah[mh], ao);
                }
                #pragma unroll
                for (int g = 0; g < 4; g++){
                    uint32_t bo = wb + (uint32_t)(
                        ((((ns*8 + g*2 + (lane>>4))*4 + 2*kh + ((lane>>3)&1))<<7) + (lane&7)*16));
                    uint32_t bh[4];
                    LDMX4(bh, bo);
                    #pragma unroll
                    for (int h2 = 0; h2 < 2; h2++)
                        #pragma unroll
                        for (int mh = 0; mh < 2; mh++){
                            float* a4 = acc + ((g*2+h2)*2 + mh)*4;
                            MMA16816(a4, ah[mh], bh[2*h2], bh[2*h2+1]);
                        }
                }
            }
            if (lane == 0) MB_ARR(mb + 32 + 8*buf);
            if (tid == 0 && c+4 < NCHUNK){
                MB_WAIT(mb + 32 + 8*buf, (cphs>>buf)&1);
                cphs ^= 1u << buf;
                MB_EXTX(mb + 8*buf, 16384);
                bulk_g2s(wb, g_ws + (long long)(c+4)*16384, 16384, mb + 8*buf);
            }
        }
        if (sg_end[s]){
            __syncthreads();   // all warps done reading A for this layer
            const float* bp = P.bias[layer];
            const int nmax = (layer == 9) ? 128 : 256;
            #pragma unroll
            for (int nti = 0; nti < 8; nti++)
                #pragma unroll
                for (int mh = 0; mh < 2; mh++){
                    float* a4 = acc + (nti*2 + mh)*4;
                    int n0 = ns*64 + nti*8 + (lane&3)*2;
                    int mr = ms*32 + mh*16 + (lane>>2);
                    float b0 = (n0 < nmax) ? __ldg(bp + n0) : 0.f;
                    float b1 = (n0+1 < nmax) ? __ldg(bp + n0 + 1) : 0.f;
                    int ktw = ns*8 + nti;
                    float v0 = fmaxf(a4[0]+b0,0.f), v1 = fmaxf(a4[1]+b1,0.f);
                    float v2 = fmaxf(a4[2]+b0,0.f), v3 = fmaxf(a4[3]+b1,0.f);
                    uint32_t o0 = (uint32_t)((((mr>>3)*40 + ktw)<<7) + (mr&7)*16 + (lane&3)*4);
                    int m2 = mr + 8;
                    uint32_t o1 = (uint32_t)((((m2>>3)*40 + ktw)<<7) + (m2&7)*16 + (lane&3)*4);
                    *(uint32_t*)(smem+SM_A+o0) = packh2(v0, v1);
                    *(uint32_t*)(smem+SM_A+o1) = packh2(v2, v3);
                }
            if (layer == 5){
                for (int idx = tid; idx < 64*27; idx += 256){
                    int m = idx/27, k = idx - m*27;
                    store_a(smem, m, 256+k, embed_val(P.dirs, gp0, m, k));
                }
            }
            __syncthreads();
            if (layer == 7 && tid < 64){
                int m = tid; float ssum = __ldg(P.bsig);
                #pragma unroll 8
                for (int k = 0; k < 256; k++) ssum = fmaf(read_a(smem, m, k), __ldg(P.Wsig + k), ssum);
                P.out[3*N + gp0 + m] = ssum;
            }
            if (layer == 9 && tid < 64){
                int m = tid;
                float r0 = __ldg(P.br1+0), r1 = __ldg(P.br1+1), r2 = __ldg(P.br1+2);
                #pragma unroll 8
                for (int k = 0; k < 128; k++){
                    float av = read_a(smem, m, k);
                    r0 = fmaf(av, __ldg(P.Wr1 + k), r0);
                    r1 = fmaf(av, __ldg(P.Wr1 + 128 + k), r1);
                    r2 = fmaf(av, __ldg(P.Wr1 + 256 + k), r2);
                }
                long long gm = gp0 + m;
                P.out[gm*3+0] = 1.f/(1.f + expf(-r0));
                P.out[gm*3+1] = 1.f/(1.f + expf(-r1));
                P.out[gm*3+2] = 1.f/(1.f + expf(-r2));
            }
        }
    }
}

extern "C" void kernel_launch(void* const* d_in, const int* in_sizes, int n_in,
                              void* d_out, int out_size)
{
    PrepParams pp;
    for (int i = 0; i < 8; i++) pp.w[i] = (const float*)d_in[2 + 2*i];
    pp.w[8] = (const float*)d_in[20];
    pp.w[9] = (const float*)d_in[22];

    MainParams mp;
    mp.pts  = (const float*)d_in[0];
    mp.dirs = (const float*)d_in[1];
    for (int i = 0; i < 8; i++) mp.bias[i] = (const float*)d_in[3 + 2*i];
    mp.bias[8] = (const float*)d_in[21];     // brm
    mp.bias[9] = (const float*)d_in[23];     // br0
    mp.Wsig = (const float*)d_in[18]; mp.bsig = (const float*)d_in[19];
    mp.Wr1  = (const float*)d_in[24]; mp.br1  = (const float*)d_in[25];
    mp.out  = (float*)d_out;
    mp.N    = in_sizes[0] / 3;

    prep<<<NCHUNK, 256>>>(pp);
    cudaFuncSetAttribute(nerf_mma, cudaFuncAttributeMaxDynamicSharedMemorySize, SM_TOTAL);
    nerf_mma<<<mp.N/64, 256, SM_TOTAL>>>(mp);
}

// round 14
// speedup vs baseline: 16.9408x; 1.0850x over previous
#include <cuda_runtime.h>
#include <cuda_fp16.h>
#include <cstdint>
#include <math.h>

#define NCHUNK 77
#define SM_A    0
#define SM_W    40960
#define SM_MBAR 106496
#define SM_TOTAL 106624

__device__ __forceinline__ uint32_t smem_u32(const void* p){
    uint32_t a; asm("{ .reg .u64 t; cvta.to.shared.u64 t, %1; cvt.u32.u64 %0, t; }" : "=r"(a) : "l"(p)); return a;
}
#define MB_INIT(m,c) asm volatile("mbarrier.init.shared.b64 [%0], %1;" :: "r"(m), "r"((uint32_t)(c)) : "memory")
#define MB_EXTX(m,b) asm volatile("mbarrier.arrive.expect_tx.shared.b64 _, [%0], %1;" :: "r"(m), "r"((uint32_t)(b)) : "memory")
#define MB_ARR(m)    asm volatile("mbarrier.arrive.shared.b64 _, [%0];" :: "r"(m) : "memory")
#define MB_WAIT(m,ph) do{ uint32_t _m=(m),_p=(ph),_d; \
    asm volatile("{\n\t.reg .pred p;\n\tmbarrier.try_wait.parity.acquire.cta.shared::cta.b64 p, [%1], %2;\n\tselp.b32 %0,1,0,p;\n\t}" : "=r"(_d) : "r"(_m), "r"(_p) : "memory"); \
    if(!_d){ asm volatile("{\n\t.reg .pred P1;\n\tWL_%=:\n\tmbarrier.try_wait.parity.acquire.cta.shared::cta.b64 P1, [%0], %1, 0x989680;\n\t@P1 bra.uni WD_%=;\n\tbra.uni WL_%=;\n\tWD_%=:\n\t}" :: "r"(_m), "r"(_p) : "memory"); } }while(0)
__device__ __forceinline__ void bulk_g2s(uint32_t dst, const void* src, uint32_t bytes, uint32_t mbar){
    asm volatile("cp.async.bulk.shared::cluster.global.mbarrier::complete_tx::bytes [%0], [%1], %2, [%3];"
        :: "r"(dst), "l"(src), "r"(bytes), "r"(mbar) : "memory");
}
#define LDMX4(r,a) asm volatile("ldmatrix.sync.aligned.m8n8.x4.shared.b16 {%0,%1,%2,%3}, [%4];" \
    : "=r"((r)[0]),"=r"((r)[1]),"=r"((r)[2]),"=r"((r)[3]) : "r"(a))
#define MMA16816(c,a,b0,b1) asm volatile( \
    "mma.sync.aligned.m16n8k16.row.col.f32.f16.f16.f32 {%0,%1,%2,%3},{%4,%5,%6,%7},{%8,%9},{%0,%1,%2,%3};" \
    : "+f"((c)[0]),"+f"((c)[1]),"+f"((c)[2]),"+f"((c)[3]) \
    : "r"((a)[0]),"r"((a)[1]),"r"((a)[2]),"r"((a)[3]), "r"(b0),"r"(b1))

__device__ __forceinline__ uint32_t packh2(float v0, float v1){
    __half2 h = __floats2half2_rn(v0, v1);
    return *reinterpret_cast<uint32_t*>(&h);
}

// segment tables: 12 segments over 10 GEMM layers, k32 chunks
__constant__ unsigned char sg_layer[12]={0,1,2,3,4,5,5,6,7,8,9,9};
__constant__ short sg_cnt[12]={2,8,8,8,8,2,8,8,8,8,8,1};
__constant__ short sg_cum[12]={0,2,10,18,26,34,36,44,52,60,68,76};
__constant__ unsigned char sg_akt[12]={32,0,0,0,0,32,0,0,0,0,0,32};
__constant__ unsigned char sg_first[12]={1,1,1,1,1,1,0,1,1,1,1,0};
__constant__ unsigned char sg_end[12]={1,1,1,1,1,0,1,1,1,1,0,1};
__constant__ unsigned char sg_w[12]={0,1,2,3,4,5,5,6,7,8,9,9};
__constant__ short sg_wcol[12]={0,0,0,0,0,0,63,0,0,0,0,256};
__constant__ short sg_kmax[12]={63,256,256,256,256,63,256,256,256,256,256,27};
__constant__ short sg_wstr[12]={63,256,256,256,256,319,319,256,256,256,283,283};
__constant__ short sg_nval[12]={256,256,256,256,256,256,256,256,256,256,128,128};

__device__ __align__(1024) unsigned char g_ws[NCHUNK*16384];

struct PrepParams { const float* w[10]; };
__global__ void prep(PrepParams pp){
    int c = blockIdx.x, s = 11;
    for (int i = 1; i < 12; i++) if (c < sg_cum[i]){ s = i-1; break; }
    int ci = c - sg_cum[s];
    const float* W = pp.w[sg_w[s]];
    int kval = sg_kmax[s] - 32*ci; if (kval > 32) kval = 32;
    int nval = sg_nval[s], ws = sg_wstr[s], col0 = sg_wcol[s] + ci*32;
    unsigned char* dst = g_ws + (long long)c*16384;
    for (int idx = threadIdx.x; idx < 8192; idx += blockDim.x){
        int n = idx>>5, kk = idx&31;
        float w = (kk < kval && n < nval) ? W[n*ws + col0 + kk] : 0.f;
        uint32_t off = (uint32_t)((((n>>3)*4 + (kk>>3))<<7) + ((n&7)<<4) + ((kk&7)<<1));
        *(__half*)(dst+off) = __float2half_rn(w);
    }
}

struct MainParams {
    const float* pts; const float* dirs;
    const float* bias[10];           // bb0..7, brm, br0
    const float* Wsig; const float* bsig;
    const float* Wr1;  const float* br1;
    float* out; int N;
};

__device__ __forceinline__ float embed_val(const float* base, int g0, int m, int k){
    if (k < 3) return base[(g0+m)*3+k];
    int q = k-3, f = q/6, rr = q - f*6, d = rr%3;
    float x = base[(g0+m)*3+d] * (float)(1<<f);
    return (rr < 3) ? sinf(x) : cosf(x);
}
__device__ __forceinline__ void store_a(unsigned char* smem, int m, int col, float v){
    uint32_t off = (uint32_t)((((m>>3)*40 + (col>>3))<<7) + (m&7)*16 + (col&7)*2);
    *(__half*)(smem+SM_A+off) = __float2half_rn(v);
}
__device__ __forceinline__ float read_a(const unsigned char* smem, int m, int k){
    uint32_t off = (uint32_t)((((m>>3)*40 + (k>>3))<<7) + (m&7)*16 + (k&7)*2);
    return __half2float(*(const __half*)(smem+SM_A+off));
}

__global__ void __launch_bounds__(256,2) nerf_mma(MainParams P)
{
    extern __shared__ __align__(1024) unsigned char smem[];
    const uint32_t sb = smem_u32(smem), mb = sb + SM_MBAR;
    // mb+0..24: full[0..3]   mb+32..56: cons[0..3] (count 8)
    const int tid = threadIdx.x, lane = tid&31, wid = tid>>5;
    const int ms = wid&1, ns = wid>>1;       // 2 m-blocks x 4 n-blocks
    const int gp0 = blockIdx.x*64;
    const long long N = P.N;

    // per-warp constant SMEM bases (strength-reduced addressing)
    const uint32_t abase = sb + SM_A +
        (uint32_t)(((ms*4 + ((lane>>3)&1))*40 + (lane>>4))*128 + (lane&7)*16);
    const uint32_t bbase =
        (uint32_t)((ns*8 + (lane>>4))*512 + ((lane>>3)&1)*128 + (lane&7)*16);

    if (tid == 0){
        MB_INIT(mb,1); MB_INIT(mb+8,1); MB_INIT(mb+16,1); MB_INIT(mb+24,1);
        MB_INIT(mb+32,8); MB_INIT(mb+40,8); MB_INIT(mb+48,8); MB_INIT(mb+56,8);
    }
    __syncthreads();
    if (tid == 0){
        #pragma unroll
        for (int b = 0; b < 4; b++){
            MB_EXTX(mb + 8*b, 16384);
            bulk_g2s(sb + SM_W + b*16384, g_ws + (long long)b*16384, 16384, mb + 8*b);
        }
    }
    // zero A plane (40960 B)
    for (int i = tid*16; i < 40960; i += 256*16) *(uint4*)(smem+i) = make_uint4(0,0,0,0);
    __syncthreads();
    for (int idx = tid; idx < 64*63; idx += 256){
        int m = idx/63, k = idx - m*63;
        store_a(smem, m, 256+k, embed_val(P.pts, gp0, m, k));
    }
    {
        float* outD = P.out + 4*N;
        for (int idx = tid; idx < 64*27; idx += 256){
            int m = idx/27, k = idx - m*27;
            outD[(long long)(gp0+m)*27 + k] = embed_val(P.dirs, gp0, m, k);
        }
    }
    __syncthreads();

    float acc[64];
    int c = 0; uint32_t phs = 0, cphs = 0;
    #pragma unroll 1
    for (int s = 0; s < 12; s++){
        const int cnt = sg_cnt[s], layer = sg_layer[s];
        const bool act = (sg_nval[s] == 256) || (ns < 2);   // skip zero-padded head halves
        uint32_t koff = (uint32_t)sg_akt[s] * 128;
        if (sg_first[s]){
            #pragma unroll
            for (int i = 0; i < 64; i++) acc[i] = 0.f;
        }
        #pragma unroll 1
        for (int ci = 0; ci < cnt; ci++, c++){
            int buf = c & 3;
            MB_WAIT(mb + 8*buf, (phs>>buf)&1);
            phs ^= 1u << buf;
            if (act){
                const uint32_t ka = abase + koff;
                const uint32_t wbb = sb + SM_W + buf*16384 + bbase;
                uint32_t af[4][4];
                #pragma unroll
                for (int kh = 0; kh < 2; kh++)
                    #pragma unroll
                    for (int mh = 0; mh < 2; mh++)
                        LDMX4(af[kh*2+mh], ka + kh*256 + mh*10240);
                #pragma unroll
                for (int kh = 0; kh < 2; kh++)
                    #pragma unroll
                    for (int g = 0; g < 4; g++){
                        uint32_t bh[4];
                        LDMX4(bh, wbb + g*1024 + kh*256);
                        MMA16816(acc + ((g*2+0)*2+0)*4, af[kh*2+0], bh[0], bh[1]);
                        MMA16816(acc + ((g*2+0)*2+1)*4, af[kh*2+1], bh[0], bh[1]);
                        MMA16816(acc + ((g*2+1)*2+0)*4, af[kh*2+0], bh[2], bh[3]);
                        MMA16816(acc + ((g*2+1)*2+1)*4, af[kh*2+1], bh[2], bh[3]);
                    }
            }
            koff += 512;
            if (lane == 0) MB_ARR(mb + 32 + 8*buf);
            if (tid == 0 && c+4 < NCHUNK){
                MB_WAIT(mb + 32 + 8*buf, (cphs>>buf)&1);
                cphs ^= 1u << buf;
                MB_EXTX(mb + 8*buf, 16384);
                bulk_g2s(sb + SM_W + buf*16384, g_ws + (long long)(c+4)*16384, 16384, mb + 8*buf);
            }
        }
        if (sg_end[s]){
            __syncthreads();   // all warps done reading A for this layer
            const float* bp = P.bias[layer];
            const int nmax = (layer == 9) ? 128 : 256;
            if (act){
                #pragma unroll
                for (int nti = 0; nti < 8; nti++)
                    #pragma unroll
                    for (int mh = 0; mh < 2; mh++){
                        float* a4 = acc + (nti*2 + mh)*4;
                        int n0 = ns*64 + nti*8 + (lane&3)*2;
                        int mr = ms*32 + mh*16 + (lane>>2);
                        float b0 = (n0 < nmax) ? __ldg(bp + n0) : 0.f;
                        float b1 = (n0+1 < nmax) ? __ldg(bp + n0 + 1) : 0.f;
                        int ktw = ns*8 + nti;
                        float v0 = fmaxf(a4[0]+b0,0.f), v1 = fmaxf(a4[1]+b1,0.f);
                        float v2 = fmaxf(a4[2]+b0,0.f), v3 = fmaxf(a4[3]+b1,0.f);
                        uint32_t o0 = (uint32_t)((((mr>>3)*40 + ktw)<<7) + (mr&7)*16 + (lane&3)*4);
                        int m2 = mr + 8;
                        uint32_t o1 = (uint32_t)((((m2>>3)*40 + ktw)<<7) + (m2&7)*16 + (lane&3)*4);
                        *(uint32_t*)(smem+SM_A+o0) = packh2(v0, v1);
                        *(uint32_t*)(smem+SM_A+o1) = packh2(v2, v3);
                    }
            }
            if (layer == 5){
                for (int idx = tid; idx < 64*27; idx += 256){
                    int m = idx/27, k = idx - m*27;
                    store_a(smem, m, 256+k, embed_val(P.dirs, gp0, m, k));
                }
            }
            __syncthreads();
            if (layer == 7 && tid < 64){
                int m = tid; float ssum = __ldg(P.bsig);
                #pragma unroll 8
                for (int k = 0; k < 256; k++) ssum = fmaf(read_a(smem, m, k), __ldg(P.Wsig + k), ssum);
                P.out[3*N + gp0 + m] = ssum;
            }
            if (layer == 9 && tid < 64){
                int m = tid;
                float r0 = __ldg(P.br1+0), r1 = __ldg(P.br1+1), r2 = __ldg(P.br1+2);
                #pragma unroll 8
                for (int k = 0; k < 128; k++){
                    float av = read_a(smem, m, k);
                    r0 = fmaf(av, __ldg(P.Wr1 + k), r0);
                    r1 = fmaf(av, __ldg(P.Wr1 + 128 + k), r1);
                    r2 = fmaf(av, __ldg(P.Wr1 + 256 + k), r2);
                }
                long long gm = gp0 + m;
                P.out[gm*3+0] = 1.f/(1.f + expf(-r0));
                P.out[gm*3+1] = 1.f/(1.f + expf(-r1));
                P.out[gm*3+2] = 1.f/(1.f + expf(-r2));
            }
        }
    }
}

extern "C" void kernel_launch(void* const* d_in, const int* in_sizes, int n_in,
                              void* d_out, int out_size)
{
    PrepParams pp;
    for (int i = 0; i < 8; i++) pp.w[i] = (const float*)d_in[2 + 2*i];
    pp.w[8] = (const float*)d_in[20];
    pp.w[9] = (const float*)d_in[22];

    MainParams mp;
    mp.pts  = (const float*)d_in[0];
    mp.dirs = (const float*)d_in[1];
    for (int i = 0; i < 8; i++) mp.bias[i] = (const float*)d_in[3 + 2*i];
    mp.bias[8] = (const float*)d_in[21];     // brm
    mp.bias[9] = (const float*)d_in[23];     // br0
    mp.Wsig = (const float*)d_in[18]; mp.bsig = (const float*)d_in[19];
    mp.Wr1  = (const float*)d_in[24]; mp.br1  = (const float*)d_in[25];
    mp.out  = (float*)d_out;
    mp.N    = in_sizes[0] / 3;

    prep<<<NCHUNK, 256>>>(pp);
    cudaFuncSetAttribute(nerf_mma, cudaFuncAttributeMaxDynamicSharedMemorySize, SM_TOTAL);
    nerf_mma<<<mp.N/64, 256, SM_TOTAL>>>(mp);
}